// round 1
// baseline (speedup 1.0000x reference)
#include <cuda_runtime.h>
#include <cuda_bf16.h>
#include <math.h>

// Problem constants
#define T_DIM 8192
#define H_DIM 2048
#define D_DIM 1024

#define CHUNK 128
#define NCHUNK (T_DIM / CHUNK)   // 64

// 64 MB scratch for u = x @ B^T  (allocation-free: __device__ global)
__device__ float g_u[(size_t)T_DIM * H_DIM];
__device__ float g_carry[NCHUNK * H_DIM];  // chunk-local end states (zero init)
__device__ float g_init[NCHUNK * H_DIM];   // exact init state for each chunk

// ---------------------------------------------------------------------------
// GEMM: u[t,h] = sum_d x[t,d] * B[h,d]
// x: [T, D] row-major, B: [H, D] row-major (both K-contiguous: NT GEMM)
// Tiles: 128 (T) x 128 (H) x 16 (K). 256 threads, 8x8 microtile per thread.
// ---------------------------------------------------------------------------
#define BT 128
#define BH 128
#define BK 16

__global__ __launch_bounds__(256, 2)
void gemm_kernel(const float* __restrict__ x, const float* __restrict__ Bm) {
    __shared__ float As[BK][BT];  // [k][t]
    __shared__ float Bs[BK][BH];  // [k][h]

    const int tid = threadIdx.x;
    const int h0 = blockIdx.x * BH;
    const int t0 = blockIdx.y * BT;

    const int tx = tid % 16;  // h direction
    const int ty = tid / 16;  // t direction

    float acc[8][8];
#pragma unroll
    for (int i = 0; i < 8; ++i)
#pragma unroll
        for (int j = 0; j < 8; ++j) acc[i][j] = 0.0f;

    for (int k0 = 0; k0 < D_DIM; k0 += BK) {
        // Load tiles: 128 rows x 16 floats = 512 float4 each; 2 per thread.
#pragma unroll
        for (int s = 0; s < 2; ++s) {
            int j = s * 256 + tid;
            int row = j >> 2;        // 0..127
            int c4  = j & 3;         // 0..3 -> k offset c4*4
            float4 va = *reinterpret_cast<const float4*>(
                &x[(size_t)(t0 + row) * D_DIM + k0 + c4 * 4]);
            As[c4 * 4 + 0][row] = va.x;
            As[c4 * 4 + 1][row] = va.y;
            As[c4 * 4 + 2][row] = va.z;
            As[c4 * 4 + 3][row] = va.w;
            float4 vb = *reinterpret_cast<const float4*>(
                &Bm[(size_t)(h0 + row) * D_DIM + k0 + c4 * 4]);
            Bs[c4 * 4 + 0][row] = vb.x;
            Bs[c4 * 4 + 1][row] = vb.y;
            Bs[c4 * 4 + 2][row] = vb.z;
            Bs[c4 * 4 + 3][row] = vb.w;
        }
        __syncthreads();

#pragma unroll
        for (int kk = 0; kk < BK; ++kk) {
            float a[8], b[8];
            *reinterpret_cast<float4*>(a)     = *reinterpret_cast<const float4*>(&As[kk][ty * 8]);
            *reinterpret_cast<float4*>(a + 4) = *reinterpret_cast<const float4*>(&As[kk][ty * 8 + 4]);
            *reinterpret_cast<float4*>(b)     = *reinterpret_cast<const float4*>(&Bs[kk][tx * 8]);
            *reinterpret_cast<float4*>(b + 4) = *reinterpret_cast<const float4*>(&Bs[kk][tx * 8 + 4]);
#pragma unroll
            for (int i = 0; i < 8; ++i)
#pragma unroll
                for (int j = 0; j < 8; ++j)
                    acc[i][j] = fmaf(a[i], b[j], acc[i][j]);
        }
        __syncthreads();
    }

    // Store 8x8 microtile to g_u (coalesced float4 along H)
#pragma unroll
    for (int i = 0; i < 8; ++i) {
        size_t rowbase = (size_t)(t0 + ty * 8 + i) * H_DIM + h0 + tx * 8;
        float4 v0 = make_float4(acc[i][0], acc[i][1], acc[i][2], acc[i][3]);
        float4 v1 = make_float4(acc[i][4], acc[i][5], acc[i][6], acc[i][7]);
        *reinterpret_cast<float4*>(&g_u[rowbase])     = v0;
        *reinterpret_cast<float4*>(&g_u[rowbase + 4]) = v1;
    }
}

// ---------------------------------------------------------------------------
// Scan pass 1: per (chunk, h), compute chunk-local end state with zero init.
// ---------------------------------------------------------------------------
__global__ __launch_bounds__(256)
void carry_kernel(const float* __restrict__ lamda) {
    const int h = blockIdx.x * blockDim.x + threadIdx.x;
    const int c = blockIdx.y;
    if (h >= H_DIM) return;
    const float a = 1.0f / (1.0f + expf(-lamda[h]));
    const float* up = g_u + (size_t)c * CHUNK * H_DIM + h;
    float s = 0.0f;
#pragma unroll 8
    for (int t = 0; t < CHUNK; ++t) {
        s = fmaf(a, s, up[(size_t)t * H_DIM]);
    }
    g_carry[c * H_DIM + h] = s;
}

// ---------------------------------------------------------------------------
// Scan pass 2: sequential combine over the 64 chunk carries.
// init[c] = end-state of chunk c-1;  end[c] = a^C * end[c-1] + carry[c]
// ---------------------------------------------------------------------------
__global__ __launch_bounds__(256)
void combine_kernel(const float* __restrict__ lamda) {
    const int h = blockIdx.x * blockDim.x + threadIdx.x;
    if (h >= H_DIM) return;
    const float a = 1.0f / (1.0f + expf(-lamda[h]));
    float aC = a;
#pragma unroll
    for (int i = 0; i < 7; ++i) aC *= aC;  // a^(2^7) = a^128 = a^CHUNK
    float state = 0.0f;
    for (int c = 0; c < NCHUNK; ++c) {
        g_init[c * H_DIM + h] = state;
        state = fmaf(aC, state, g_carry[c * H_DIM + h]);
    }
}

// ---------------------------------------------------------------------------
// Scan pass 3: per (chunk, h), rerun recurrence with exact init, write output.
// ---------------------------------------------------------------------------
__global__ __launch_bounds__(256)
void apply_kernel(const float* __restrict__ lamda, float* __restrict__ out) {
    const int h = blockIdx.x * blockDim.x + threadIdx.x;
    const int c = blockIdx.y;
    if (h >= H_DIM) return;
    const float a = 1.0f / (1.0f + expf(-lamda[h]));
    float s = g_init[c * H_DIM + h];
    const size_t base = (size_t)c * CHUNK * H_DIM + h;
#pragma unroll 8
    for (int t = 0; t < CHUNK; ++t) {
        s = fmaf(a, s, g_u[base + (size_t)t * H_DIM]);
        out[base + (size_t)t * H_DIM] = s;
    }
}

// ---------------------------------------------------------------------------
extern "C" void kernel_launch(void* const* d_in, const int* in_sizes, int n_in,
                              void* d_out, int out_size) {
    const float* x     = (const float*)d_in[0];  // [T, D]
    const float* lamda = (const float*)d_in[1];  // [H]
    const float* Bm    = (const float*)d_in[2];  // [H, D]
    float* out = (float*)d_out;                  // [T, H]

    dim3 ggrid(H_DIM / BH, T_DIM / BT);
    gemm_kernel<<<ggrid, 256>>>(x, Bm);

    dim3 sgrid(H_DIM / 256, NCHUNK);
    carry_kernel<<<sgrid, 256>>>(lamda);
    combine_kernel<<<H_DIM / 256, 256>>>(lamda);
    apply_kernel<<<sgrid, 256>>>(lamda, out);
}

// round 3
// speedup vs baseline: 2.2545x; 2.2545x over previous
#include <cuda_runtime.h>
#include <cuda_bf16.h>
#include <math.h>
#include <stdint.h>

// Problem constants
#define T_DIM 8192
#define H_DIM 2048
#define D_DIM 1024

// Packed bf16 layout: per row of 1024 original k, 32 blocks of [hi(32) | lo(32)]
#define KPACK 2048
#define KPACK_BYTES (KPACK * 2)

#define CHUNK 128
#define NCHUNK (T_DIM / CHUNK)   // 64

// Scratch (allocation-free: __device__ globals)
__device__ float          g_u[(size_t)T_DIM * H_DIM];       // 64 MB
__device__ __nv_bfloat16  g_Ax[(size_t)T_DIM * KPACK];      // 32 MB
__device__ __nv_bfloat16  g_Bx[(size_t)H_DIM * KPACK];      // 8 MB
__device__ float          g_carry[NCHUNK * H_DIM];
__device__ float          g_init[NCHUNK * H_DIM];

// ---------------------------------------------------------------------------
// helpers
// ---------------------------------------------------------------------------
__device__ __forceinline__ uint32_t smem_u32(const void* p) {
    uint32_t a;
    asm("{ .reg .u64 t; cvta.to.shared.u64 t, %1; cvt.u32.u64 %0, t; }" : "=r"(a) : "l"(p));
    return a;
}
#define CP_ASYNC16(dst, src) \
    asm volatile("cp.async.cg.shared.global [%0], [%1], 16;" :: "r"(dst), "l"(src))
#define CP_COMMIT() asm volatile("cp.async.commit_group;" ::: "memory")
template<int N> __device__ __forceinline__ void cp_wait() {
    asm volatile("cp.async.wait_group %0;" :: "n"(N) : "memory");
}
__device__ __forceinline__ uint32_t swz128(uint32_t off) { return off ^ ((off >> 3) & 0x70); }

#define LDSM_X4(r, addr) \
    asm volatile("ldmatrix.sync.aligned.m8n8.x4.shared.b16 {%0,%1,%2,%3}, [%4];" \
                 : "=r"((r)[0]), "=r"((r)[1]), "=r"((r)[2]), "=r"((r)[3]) : "r"(addr))

#define MMA_BF16(c, a, b0, b1) \
    asm volatile("mma.sync.aligned.m16n8k16.row.col.f32.bf16.bf16.f32 " \
                 "{%0,%1,%2,%3}, {%4,%5,%6,%7}, {%8,%9}, {%0,%1,%2,%3};" \
                 : "+f"((c)[0]), "+f"((c)[1]), "+f"((c)[2]), "+f"((c)[3]) \
                 : "r"((a)[0]), "r"((a)[1]), "r"((a)[2]), "r"((a)[3]), "r"(b0), "r"(b1))

// ---------------------------------------------------------------------------
// Conversion: fp32 -> bf16 hi/lo split, packed as 32-blocks [hi32 | lo32]
// ---------------------------------------------------------------------------
__device__ __forceinline__ void split4(float4 v, __nv_bfloat162& hA, __nv_bfloat162& hB,
                                       __nv_bfloat162& lA, __nv_bfloat162& lB) {
    __nv_bfloat16 h0 = __float2bfloat16_rn(v.x), h1 = __float2bfloat16_rn(v.y);
    __nv_bfloat16 h2 = __float2bfloat16_rn(v.z), h3 = __float2bfloat16_rn(v.w);
    __nv_bfloat16 l0 = __float2bfloat16_rn(v.x - __bfloat162float(h0));
    __nv_bfloat16 l1 = __float2bfloat16_rn(v.y - __bfloat162float(h1));
    __nv_bfloat16 l2 = __float2bfloat16_rn(v.z - __bfloat162float(h2));
    __nv_bfloat16 l3 = __float2bfloat16_rn(v.w - __bfloat162float(h3));
    hA = __nv_bfloat162(h0, h1); hB = __nv_bfloat162(h2, h3);
    lA = __nv_bfloat162(l0, l1); lB = __nv_bfloat162(l2, l3);
}

__global__ __launch_bounds__(256)
void convert_x_kernel(const float* __restrict__ x) {
    size_t i4 = (size_t)blockIdx.x * blockDim.x + threadIdx.x;
    size_t base = i4 * 4;
    size_t t = base / D_DIM;
    int    d = (int)(base % D_DIM);
    int blk = d >> 5, pos = d & 31;
    float4 v = *reinterpret_cast<const float4*>(&x[base]);
    __nv_bfloat162 hA, hB, lA, lB;
    split4(v, hA, hB, lA, lB);
    __nv_bfloat162* ph = reinterpret_cast<__nv_bfloat162*>(&g_Ax[t * KPACK + blk * 64 + pos]);
    __nv_bfloat162* pl = reinterpret_cast<__nv_bfloat162*>(&g_Ax[t * KPACK + blk * 64 + 32 + pos]);
    ph[0] = hA; ph[1] = hB;
    pl[0] = lA; pl[1] = lB;
}

__global__ __launch_bounds__(256)
void convert_B_kernel(const float* __restrict__ Bm) {
    size_t i4 = (size_t)blockIdx.x * blockDim.x + threadIdx.x;
    size_t base = i4 * 4;
    size_t h = base / D_DIM;
    int    d = (int)(base % D_DIM);
    int blk = d >> 5, pos = d & 31;
    float4 v = *reinterpret_cast<const float4*>(&Bm[base]);
    __nv_bfloat162 hA, hB, lA, lB;
    split4(v, hA, hB, lA, lB);
    __nv_bfloat162* ph = reinterpret_cast<__nv_bfloat162*>(&g_Bx[h * KPACK + blk * 64 + pos]);
    __nv_bfloat162* pl = reinterpret_cast<__nv_bfloat162*>(&g_Bx[h * KPACK + blk * 64 + 32 + pos]);
    ph[0] = hA; ph[1] = hB;
    pl[0] = lA; pl[1] = lB;
}

// ---------------------------------------------------------------------------
// bf16 mma.sync GEMM with 3-term split:
//   u = x_hi*B_hi + x_lo*B_hi + x_hi*B_lo   (fp32 accumulate)
// Block tile 128x128, 256 threads (2x4 warps), warp tile 64x32.
// K stage = 32 original k -> 128B/row ([hi32|lo32]); 3-stage cp.async pipeline.
// ---------------------------------------------------------------------------
#define BM 128
#define BN 128
#define A_STAGE 16384
#define B_STAGE 16384
#define STAGE_BYTES (A_STAGE + B_STAGE)   // 32 KB
#define NPIPE 3
#define SMEM_TOTAL (NPIPE * STAGE_BYTES)  // 96 KB
#define KSTAGES (D_DIM / 32)              // 32

__global__ __launch_bounds__(256, 1)
void gemm_mma_kernel() {
    extern __shared__ char smem[];
    const uint32_t sb = smem_u32(smem);
    const int tid = threadIdx.x;
    const int wid = tid >> 5, lane = tid & 31;
    const int warp_m = wid >> 2;          // 0..1
    const int warp_n = wid & 3;           // 0..3

    const int h0 = blockIdx.x * BN;
    const int t0 = blockIdx.y * BM;

    const char* Ab = reinterpret_cast<const char*>(g_Ax) + (size_t)t0 * KPACK_BYTES;
    const char* Bb = reinterpret_cast<const char*>(g_Bx) + (size_t)h0 * KPACK_BYTES;

    auto load_stage = [&](int s, int buf) {
        const uint32_t ab = sb + buf * STAGE_BYTES;
        const uint32_t bb = ab + A_STAGE;
        const size_t kbyte = (size_t)s * 128;
#pragma unroll
        for (int i = 0; i < 4; ++i) {      // A: 1024 16B chunks / 256 thr
            int j = i * 256 + tid;
            int row = j >> 3, cb = j & 7;
            uint32_t off = swz128((uint32_t)(row * 128 + cb * 16));
            CP_ASYNC16(ab + off, Ab + (size_t)row * KPACK_BYTES + kbyte + cb * 16);
        }
#pragma unroll
        for (int i = 0; i < 4; ++i) {      // B
            int j = i * 256 + tid;
            int row = j >> 3, cb = j & 7;
            uint32_t off = swz128((uint32_t)(row * 128 + cb * 16));
            CP_ASYNC16(bb + off, Bb + (size_t)row * KPACK_BYTES + kbyte + cb * 16);
        }
        CP_COMMIT();
    };

    float acc[4][4][4];
#pragma unroll
    for (int i = 0; i < 4; ++i)
#pragma unroll
        for (int j = 0; j < 4; ++j)
#pragma unroll
            for (int q = 0; q < 4; ++q) acc[i][j][q] = 0.0f;

    load_stage(0, 0);
    load_stage(1, 1);

    for (int s = 0; s < KSTAGES; ++s) {
        cp_wait<1>();            // stage s resident
        __syncthreads();         // all warps done with buffer (s+2)%3 from iter s-1
        if (s + 2 < KSTAGES) load_stage(s + 2, (s + 2) % NPIPE);
        else CP_COMMIT();        // keep group count invariant

        const uint32_t ab = sb + (s % NPIPE) * STAGE_BYTES;
        const uint32_t bb = ab + A_STAGE;

#pragma unroll
        for (int step = 0; step < 2; ++step) {   // two k16 steps per stage
            const uint32_t hi_base = step * 32;
            const uint32_t lo_base = 64 + step * 32;
            const uint32_t co = (uint32_t)(lane >> 4) * 16;

            uint32_t a_hi[4][4], a_lo[4][4], b_hi[2][4], b_lo[2][4];
#pragma unroll
            for (int mt = 0; mt < 4; ++mt) {
                int row = warp_m * 64 + mt * 16 + (lane & 15);
                LDSM_X4(a_hi[mt], ab + swz128((uint32_t)(row * 128) + hi_base + co));
                LDSM_X4(a_lo[mt], ab + swz128((uint32_t)(row * 128) + lo_base + co));
            }
#pragma unroll
            for (int bt = 0; bt < 2; ++bt) {
                int row = warp_n * 32 + bt * 16 + (lane & 15);
                LDSM_X4(b_hi[bt], bb + swz128((uint32_t)(row * 128) + hi_base + co));
                LDSM_X4(b_lo[bt], bb + swz128((uint32_t)(row * 128) + lo_base + co));
            }
#pragma unroll
            for (int mt = 0; mt < 4; ++mt) {
#pragma unroll
                for (int nt = 0; nt < 4; ++nt) {
                    const int bt = nt >> 1, hp = nt & 1;
                    uint32_t bh0 = b_hi[bt][hp], bh1 = b_hi[bt][2 + hp];
                    uint32_t bl0 = b_lo[bt][hp], bl1 = b_lo[bt][2 + hp];
                    MMA_BF16(acc[mt][nt], a_hi[mt], bh0, bh1);
                    MMA_BF16(acc[mt][nt], a_lo[mt], bh0, bh1);
                    MMA_BF16(acc[mt][nt], a_hi[mt], bl0, bl1);
                }
            }
        }
    }

    // Epilogue: write acc to g_u
    const int r = lane >> 2, c = (lane & 3) * 2;
    float* Cb = g_u + (size_t)(t0 + warp_m * 64) * H_DIM + h0 + warp_n * 32;
#pragma unroll
    for (int mt = 0; mt < 4; ++mt) {
#pragma unroll
        for (int nt = 0; nt < 4; ++nt) {
            float2 v0 = make_float2(acc[mt][nt][0], acc[mt][nt][1]);
            float2 v1 = make_float2(acc[mt][nt][2], acc[mt][nt][3]);
            *reinterpret_cast<float2*>(&Cb[(size_t)(mt * 16 + r) * H_DIM + nt * 8 + c]) = v0;
            *reinterpret_cast<float2*>(&Cb[(size_t)(mt * 16 + r + 8) * H_DIM + nt * 8 + c]) = v1;
        }
    }
}

// ---------------------------------------------------------------------------
// Chunked linear scan (3 passes) — exact
// ---------------------------------------------------------------------------
__global__ __launch_bounds__(256)
void carry_kernel(const float* __restrict__ lamda) {
    const int h = blockIdx.x * blockDim.x + threadIdx.x;
    const int c = blockIdx.y;
    const float a = 1.0f / (1.0f + expf(-lamda[h]));
    const float* up = g_u + (size_t)c * CHUNK * H_DIM + h;
    float s = 0.0f;
#pragma unroll 8
    for (int t = 0; t < CHUNK; ++t) s = fmaf(a, s, up[(size_t)t * H_DIM]);
    g_carry[c * H_DIM + h] = s;
}

__global__ __launch_bounds__(256)
void combine_kernel(const float* __restrict__ lamda) {
    const int h = blockIdx.x * blockDim.x + threadIdx.x;
    const float a = 1.0f / (1.0f + expf(-lamda[h]));
    float aC = a;
#pragma unroll
    for (int i = 0; i < 7; ++i) aC *= aC;  // a^128
    float state = 0.0f;
    for (int c = 0; c < NCHUNK; ++c) {
        g_init[c * H_DIM + h] = state;
        state = fmaf(aC, state, g_carry[c * H_DIM + h]);
    }
}

__global__ __launch_bounds__(256)
void apply_kernel(const float* __restrict__ lamda, float* __restrict__ out) {
    const int h = blockIdx.x * blockDim.x + threadIdx.x;
    const int c = blockIdx.y;
    const float a = 1.0f / (1.0f + expf(-lamda[h]));
    float s = g_init[c * H_DIM + h];
    const size_t base = (size_t)c * CHUNK * H_DIM + h;
#pragma unroll 8
    for (int t = 0; t < CHUNK; ++t) {
        s = fmaf(a, s, g_u[base + (size_t)t * H_DIM]);
        out[base + (size_t)t * H_DIM] = s;
    }
}

// ---------------------------------------------------------------------------
extern "C" void kernel_launch(void* const* d_in, const int* in_sizes, int n_in,
                              void* d_out, int out_size) {
    const float* x     = (const float*)d_in[0];  // [T, D]
    const float* lamda = (const float*)d_in[1];  // [H]
    const float* Bm    = (const float*)d_in[2];  // [H, D]
    float* out = (float*)d_out;                  // [T, H]

    convert_x_kernel<<<(T_DIM * D_DIM / 4) / 256, 256>>>(x);
    convert_B_kernel<<<(H_DIM * D_DIM / 4) / 256, 256>>>(Bm);

    cudaFuncSetAttribute(gemm_mma_kernel, cudaFuncAttributeMaxDynamicSharedMemorySize, SMEM_TOTAL);
    dim3 ggrid(H_DIM / BN, T_DIM / BM);   // (16, 64)
    gemm_mma_kernel<<<ggrid, 256, SMEM_TOTAL>>>();

    dim3 sgrid(H_DIM / 256, NCHUNK);
    carry_kernel<<<sgrid, 256>>>(lamda);
    combine_kernel<<<H_DIM / 256, 256>>>(lamda);
    apply_kernel<<<sgrid, 256>>>(lamda, out);
}

// round 4
// speedup vs baseline: 2.2783x; 1.0105x over previous
#include <cuda_runtime.h>
#include <cuda_bf16.h>
#include <math.h>
#include <stdint.h>

// Problem constants
#define T_DIM 8192
#define H_DIM 2048
#define D_DIM 1024

// Packed bf16 layout: per row of 1024 original k, 32 blocks of [hi(32) | lo(32)]
#define KPACK 2048
#define KPACK_BYTES (KPACK * 2)

#define CHUNK 128
#define NCHUNK (T_DIM / CHUNK)   // 64

// Scratch (allocation-free: __device__ globals)
__device__ float          g_u[(size_t)T_DIM * H_DIM];       // 64 MB
__device__ __nv_bfloat16  g_Ax[(size_t)T_DIM * KPACK];      // 32 MB
__device__ __nv_bfloat16  g_Bx[(size_t)H_DIM * KPACK];      // 8 MB
__device__ float          g_carry[NCHUNK * H_DIM];
__device__ float          g_init[NCHUNK * H_DIM];

// ---------------------------------------------------------------------------
// helpers
// ---------------------------------------------------------------------------
__device__ __forceinline__ uint32_t smem_u32(const void* p) {
    uint32_t a;
    asm("{ .reg .u64 t; cvta.to.shared.u64 t, %1; cvt.u32.u64 %0, t; }" : "=r"(a) : "l"(p));
    return a;
}
#define CP_ASYNC16(dst, src) \
    asm volatile("cp.async.cg.shared.global [%0], [%1], 16;" :: "r"(dst), "l"(src))
#define CP_COMMIT() asm volatile("cp.async.commit_group;" ::: "memory")
template<int N> __device__ __forceinline__ void cp_wait() {
    asm volatile("cp.async.wait_group %0;" :: "n"(N) : "memory");
}
__device__ __forceinline__ uint32_t swz128(uint32_t off) { return off ^ ((off >> 3) & 0x70); }

#define LDSM_X4(r, addr) \
    asm volatile("ldmatrix.sync.aligned.m8n8.x4.shared.b16 {%0,%1,%2,%3}, [%4];" \
                 : "=r"((r)[0]), "=r"((r)[1]), "=r"((r)[2]), "=r"((r)[3]) : "r"(addr))

#define MMA_BF16(c, a, b0, b1) \
    asm volatile("mma.sync.aligned.m16n8k16.row.col.f32.bf16.bf16.f32 " \
                 "{%0,%1,%2,%3}, {%4,%5,%6,%7}, {%8,%9}, {%0,%1,%2,%3};" \
                 : "+f"((c)[0]), "+f"((c)[1]), "+f"((c)[2]), "+f"((c)[3]) \
                 : "r"((a)[0]), "r"((a)[1]), "r"((a)[2]), "r"((a)[3]), "r"(b0), "r"(b1))

// ---------------------------------------------------------------------------
// Conversion: fp32 -> bf16 hi/lo split, packed as 32-blocks [hi32 | lo32]
// ---------------------------------------------------------------------------
__device__ __forceinline__ void split4(float4 v, __nv_bfloat162& hA, __nv_bfloat162& hB,
                                       __nv_bfloat162& lA, __nv_bfloat162& lB) {
    __nv_bfloat16 h0 = __float2bfloat16_rn(v.x), h1 = __float2bfloat16_rn(v.y);
    __nv_bfloat16 h2 = __float2bfloat16_rn(v.z), h3 = __float2bfloat16_rn(v.w);
    __nv_bfloat16 l0 = __float2bfloat16_rn(v.x - __bfloat162float(h0));
    __nv_bfloat16 l1 = __float2bfloat16_rn(v.y - __bfloat162float(h1));
    __nv_bfloat16 l2 = __float2bfloat16_rn(v.z - __bfloat162float(h2));
    __nv_bfloat16 l3 = __float2bfloat16_rn(v.w - __bfloat162float(h3));
    hA = __nv_bfloat162(h0, h1); hB = __nv_bfloat162(h2, h3);
    lA = __nv_bfloat162(l0, l1); lB = __nv_bfloat162(l2, l3);
}

__global__ __launch_bounds__(256)
void convert_x_kernel(const float* __restrict__ x) {
    size_t i4 = (size_t)blockIdx.x * blockDim.x + threadIdx.x;
    size_t base = i4 * 4;
    size_t t = base / D_DIM;
    int    d = (int)(base % D_DIM);
    int blk = d >> 5, pos = d & 31;
    float4 v = *reinterpret_cast<const float4*>(&x[base]);
    __nv_bfloat162 hA, hB, lA, lB;
    split4(v, hA, hB, lA, lB);
    __nv_bfloat162* ph = reinterpret_cast<__nv_bfloat162*>(&g_Ax[t * KPACK + blk * 64 + pos]);
    __nv_bfloat162* pl = reinterpret_cast<__nv_bfloat162*>(&g_Ax[t * KPACK + blk * 64 + 32 + pos]);
    ph[0] = hA; ph[1] = hB;
    pl[0] = lA; pl[1] = lB;
}

__global__ __launch_bounds__(256)
void convert_B_kernel(const float* __restrict__ Bm) {
    size_t i4 = (size_t)blockIdx.x * blockDim.x + threadIdx.x;
    size_t base = i4 * 4;
    size_t h = base / D_DIM;
    int    d = (int)(base % D_DIM);
    int blk = d >> 5, pos = d & 31;
    float4 v = *reinterpret_cast<const float4*>(&Bm[base]);
    __nv_bfloat162 hA, hB, lA, lB;
    split4(v, hA, hB, lA, lB);
    __nv_bfloat162* ph = reinterpret_cast<__nv_bfloat162*>(&g_Bx[h * KPACK + blk * 64 + pos]);
    __nv_bfloat162* pl = reinterpret_cast<__nv_bfloat162*>(&g_Bx[h * KPACK + blk * 64 + 32 + pos]);
    ph[0] = hA; ph[1] = hB;
    pl[0] = lA; pl[1] = lB;
}

// ---------------------------------------------------------------------------
// bf16 mma.sync GEMM with 3-term split (term-major issue order):
//   u = x_hi*B_hi + x_lo*B_hi + x_hi*B_lo   (fp32 accumulate)
// Block tile 128x128, 256 threads (2x4 warps), warp tile 64x32.
// 4-stage cp.async pipeline. Epilogue fuses chunk-carry computation.
// ---------------------------------------------------------------------------
#define BM 128
#define BN 128
#define A_STAGE 16384
#define B_STAGE 16384
#define STAGE_BYTES (A_STAGE + B_STAGE)   // 32 KB
#define NPIPE 4
#define SMEM_TOTAL (NPIPE * STAGE_BYTES)  // 128 KB
#define KSTAGES (D_DIM / 32)              // 32
#define CPAD 132                          // padded fp32 row stride for carry staging

__global__ __launch_bounds__(256, 1)
void gemm_mma_kernel(const float* __restrict__ lamda) {
    extern __shared__ char smem[];
    const uint32_t sb = smem_u32(smem);
    const int tid = threadIdx.x;
    const int wid = tid >> 5, lane = tid & 31;
    const int warp_m = wid >> 2;          // 0..1
    const int warp_n = wid & 3;           // 0..3

    const int h0 = blockIdx.x * BN;
    const int t0 = blockIdx.y * BM;       // == chunk * CHUNK

    const char* Ab = reinterpret_cast<const char*>(g_Ax) + (size_t)t0 * KPACK_BYTES;
    const char* Bb = reinterpret_cast<const char*>(g_Bx) + (size_t)h0 * KPACK_BYTES;

    auto load_stage = [&](int s, int buf) {
        const uint32_t ab = sb + buf * STAGE_BYTES;
        const uint32_t bb = ab + A_STAGE;
        const size_t kbyte = (size_t)s * 128;
#pragma unroll
        for (int i = 0; i < 4; ++i) {      // A: 1024 16B chunks / 256 thr
            int j = i * 256 + tid;
            int row = j >> 3, cb = j & 7;
            uint32_t off = swz128((uint32_t)(row * 128 + cb * 16));
            CP_ASYNC16(ab + off, Ab + (size_t)row * KPACK_BYTES + kbyte + cb * 16);
        }
#pragma unroll
        for (int i = 0; i < 4; ++i) {      // B
            int j = i * 256 + tid;
            int row = j >> 3, cb = j & 7;
            uint32_t off = swz128((uint32_t)(row * 128 + cb * 16));
            CP_ASYNC16(bb + off, Bb + (size_t)row * KPACK_BYTES + kbyte + cb * 16);
        }
        CP_COMMIT();
    };

    float acc[4][4][4];
#pragma unroll
    for (int i = 0; i < 4; ++i)
#pragma unroll
        for (int j = 0; j < 4; ++j)
#pragma unroll
            for (int q = 0; q < 4; ++q) acc[i][j][q] = 0.0f;

    load_stage(0, 0);
    load_stage(1, 1);
    load_stage(2, 2);

    for (int s = 0; s < KSTAGES; ++s) {
        cp_wait<2>();            // stage s resident (3 groups pending -> retire oldest)
        __syncthreads();         // all warps done with buffer (s+3)%4 (used in iter s-1)
        if (s + 3 < KSTAGES) load_stage(s + 3, (s + 3) % NPIPE);
        else CP_COMMIT();        // keep group-count invariant

        const uint32_t ab = sb + (s % NPIPE) * STAGE_BYTES;
        const uint32_t bb = ab + A_STAGE;

#pragma unroll
        for (int step = 0; step < 2; ++step) {   // two k16 steps per stage
            const uint32_t hi_base = step * 32;
            const uint32_t lo_base = 64 + step * 32;
            const uint32_t co = (uint32_t)(lane >> 4) * 16;

            uint32_t a_hi[4][4], a_lo[4][4], b_hi[2][4], b_lo[2][4];
#pragma unroll
            for (int mt = 0; mt < 4; ++mt) {
                int row = warp_m * 64 + mt * 16 + (lane & 15);
                LDSM_X4(a_hi[mt], ab + swz128((uint32_t)(row * 128) + hi_base + co));
                LDSM_X4(a_lo[mt], ab + swz128((uint32_t)(row * 128) + lo_base + co));
            }
#pragma unroll
            for (int bt = 0; bt < 2; ++bt) {
                int row = warp_n * 32 + bt * 16 + (lane & 15);
                LDSM_X4(b_hi[bt], bb + swz128((uint32_t)(row * 128) + hi_base + co));
                LDSM_X4(b_lo[bt], bb + swz128((uint32_t)(row * 128) + lo_base + co));
            }
            // Term-major: 16 independent accumulators between any acc reuse.
#pragma unroll
            for (int mt = 0; mt < 4; ++mt)
#pragma unroll
                for (int nt = 0; nt < 4; ++nt) {
                    const int bt = nt >> 1, hp = nt & 1;
                    MMA_BF16(acc[mt][nt], a_hi[mt], b_hi[bt][hp], b_hi[bt][2 + hp]);
                }
#pragma unroll
            for (int mt = 0; mt < 4; ++mt)
#pragma unroll
                for (int nt = 0; nt < 4; ++nt) {
                    const int bt = nt >> 1, hp = nt & 1;
                    MMA_BF16(acc[mt][nt], a_lo[mt], b_hi[bt][hp], b_hi[bt][2 + hp]);
                }
#pragma unroll
            for (int mt = 0; mt < 4; ++mt)
#pragma unroll
                for (int nt = 0; nt < 4; ++nt) {
                    const int bt = nt >> 1, hp = nt & 1;
                    MMA_BF16(acc[mt][nt], a_hi[mt], b_lo[bt][hp], b_lo[bt][2 + hp]);
                }
        }
    }

    // ---------------- Epilogue: write g_u + fused chunk-carry ----------------
    const int r = lane >> 2, c = (lane & 3) * 2;
    float* Cb = g_u + (size_t)(t0 + warp_m * 64) * H_DIM + h0 + warp_n * 32;
    __syncthreads();                       // pipeline smem now free for staging
    float* sf = reinterpret_cast<float*>(smem);   // [128][CPAD] fp32 staging

#pragma unroll
    for (int mt = 0; mt < 4; ++mt) {
#pragma unroll
        for (int nt = 0; nt < 4; ++nt) {
            float2 v0 = make_float2(acc[mt][nt][0], acc[mt][nt][1]);
            float2 v1 = make_float2(acc[mt][nt][2], acc[mt][nt][3]);
            const int tl0 = warp_m * 64 + mt * 16 + r;
            const int hl  = warp_n * 32 + nt * 8 + c;
            *reinterpret_cast<float2*>(&Cb[(size_t)(mt * 16 + r) * H_DIM + nt * 8 + c]) = v0;
            *reinterpret_cast<float2*>(&Cb[(size_t)(mt * 16 + r + 8) * H_DIM + nt * 8 + c]) = v1;
            *reinterpret_cast<float2*>(&sf[tl0 * CPAD + hl]) = v0;
            *reinterpret_cast<float2*>(&sf[(tl0 + 8) * CPAD + hl]) = v1;
        }
    }
    __syncthreads();

    if (tid < BN) {
        const float a = 1.0f / (1.0f + expf(-lamda[h0 + tid]));
        float sc = 0.0f;
#pragma unroll 8
        for (int t = 0; t < CHUNK; ++t) sc = fmaf(a, sc, sf[t * CPAD + tid]);
        g_carry[blockIdx.y * H_DIM + h0 + tid] = sc;
    }
}

// ---------------------------------------------------------------------------
// Scan pass 2: sequential combine over the 64 chunk carries.
// ---------------------------------------------------------------------------
__global__ __launch_bounds__(256)
void combine_kernel(const float* __restrict__ lamda) {
    const int h = blockIdx.x * blockDim.x + threadIdx.x;
    const float a = 1.0f / (1.0f + expf(-lamda[h]));
    float aC = a;
#pragma unroll
    for (int i = 0; i < 7; ++i) aC *= aC;  // a^128
    float state = 0.0f;
    for (int c = 0; c < NCHUNK; ++c) {
        g_init[c * H_DIM + h] = state;
        state = fmaf(aC, state, g_carry[c * H_DIM + h]);
    }
}

// ---------------------------------------------------------------------------
// Scan pass 3: vectorized (float4 over h), exact per-chunk rerun.
// ---------------------------------------------------------------------------
__global__ __launch_bounds__(256)
void apply_kernel(const float* __restrict__ lamda, float* __restrict__ out) {
    const int h4 = (blockIdx.x * blockDim.x + threadIdx.x) * 4;
    const int c = blockIdx.y;
    float4 lam = *reinterpret_cast<const float4*>(&lamda[h4]);
    float4 a;
    a.x = 1.0f / (1.0f + expf(-lam.x));
    a.y = 1.0f / (1.0f + expf(-lam.y));
    a.z = 1.0f / (1.0f + expf(-lam.z));
    a.w = 1.0f / (1.0f + expf(-lam.w));
    float4 s = *reinterpret_cast<const float4*>(&g_init[c * H_DIM + h4]);
    const size_t base = (size_t)c * CHUNK * H_DIM + h4;
#pragma unroll 4
    for (int t = 0; t < CHUNK; ++t) {
        float4 u = *reinterpret_cast<const float4*>(&g_u[base + (size_t)t * H_DIM]);
        s.x = fmaf(a.x, s.x, u.x);
        s.y = fmaf(a.y, s.y, u.y);
        s.z = fmaf(a.z, s.z, u.z);
        s.w = fmaf(a.w, s.w, u.w);
        *reinterpret_cast<float4*>(&out[base + (size_t)t * H_DIM]) = s;
    }
}

// ---------------------------------------------------------------------------
extern "C" void kernel_launch(void* const* d_in, const int* in_sizes, int n_in,
                              void* d_out, int out_size) {
    const float* x     = (const float*)d_in[0];  // [T, D]
    const float* lamda = (const float*)d_in[1];  // [H]
    const float* Bm    = (const float*)d_in[2];  // [H, D]
    float* out = (float*)d_out;                  // [T, H]

    convert_x_kernel<<<(T_DIM * D_DIM / 4) / 256, 256>>>(x);
    convert_B_kernel<<<(H_DIM * D_DIM / 4) / 256, 256>>>(Bm);

    cudaFuncSetAttribute(gemm_mma_kernel, cudaFuncAttributeMaxDynamicSharedMemorySize, SMEM_TOTAL);
    dim3 ggrid(H_DIM / BN, T_DIM / BM);   // (16, 64)
    gemm_mma_kernel<<<ggrid, 256, SMEM_TOTAL>>>(lamda);

    combine_kernel<<<H_DIM / 256, 256>>>(lamda);
    dim3 agrid(H_DIM / 4 / 256, NCHUNK);  // (2, 64)
    apply_kernel<<<agrid, 256>>>(lamda, out);
}

// round 5
// speedup vs baseline: 2.3782x; 1.0439x over previous
#include <cuda_runtime.h>
#include <cuda_bf16.h>
#include <math.h>
#include <stdint.h>

// Problem constants
#define T_DIM 8192
#define H_DIM 2048
#define D_DIM 1024

// Packed bf16 layout: per row of 1024 original k, 32 blocks of [hi(32) | lo(32)]
#define KPACK 2048
#define KPACK_BYTES (KPACK * 2)

#define CHUNK 128
#define NCHUNK (T_DIM / CHUNK)   // 64

// Scratch (allocation-free: __device__ globals)
__device__ float          g_u[(size_t)T_DIM * H_DIM];       // 64 MB
__device__ __nv_bfloat16  g_Ax[(size_t)T_DIM * KPACK];      // 32 MB
__device__ __nv_bfloat16  g_Bx[(size_t)H_DIM * KPACK];      // 8 MB
__device__ float          g_carry[NCHUNK * H_DIM];
__device__ float          g_init[NCHUNK * H_DIM];

// ---------------------------------------------------------------------------
// helpers
// ---------------------------------------------------------------------------
__device__ __forceinline__ uint32_t smem_u32(const void* p) {
    uint32_t a;
    asm("{ .reg .u64 t; cvta.to.shared.u64 t, %1; cvt.u32.u64 %0, t; }" : "=r"(a) : "l"(p));
    return a;
}
#define CP_ASYNC16(dst, src) \
    asm volatile("cp.async.cg.shared.global [%0], [%1], 16;" :: "r"(dst), "l"(src))
#define CP_COMMIT() asm volatile("cp.async.commit_group;" ::: "memory")
template<int N> __device__ __forceinline__ void cp_wait() {
    asm volatile("cp.async.wait_group %0;" :: "n"(N) : "memory");
}
__device__ __forceinline__ uint32_t swz128(uint32_t off) { return off ^ ((off >> 3) & 0x70); }

#define LDSM_X4(r, addr) \
    asm volatile("ldmatrix.sync.aligned.m8n8.x4.shared.b16 {%0,%1,%2,%3}, [%4];" \
                 : "=r"((r)[0]), "=r"((r)[1]), "=r"((r)[2]), "=r"((r)[3]) : "r"(addr))

#define MMA_BF16(c, a, b0, b1) \
    asm volatile("mma.sync.aligned.m16n8k16.row.col.f32.bf16.bf16.f32 " \
                 "{%0,%1,%2,%3}, {%4,%5,%6,%7}, {%8,%9}, {%0,%1,%2,%3};" \
                 : "+f"((c)[0]), "+f"((c)[1]), "+f"((c)[2]), "+f"((c)[3]) \
                 : "r"((a)[0]), "r"((a)[1]), "r"((a)[2]), "r"((a)[3]), "r"(b0), "r"(b1))

// ---------------------------------------------------------------------------
// Conversion: fp32 -> bf16 hi/lo split, packed as 32-blocks [hi32 | lo32]
// ---------------------------------------------------------------------------
__device__ __forceinline__ void split4(float4 v, __nv_bfloat162& hA, __nv_bfloat162& hB,
                                       __nv_bfloat162& lA, __nv_bfloat162& lB) {
    __nv_bfloat16 h0 = __float2bfloat16_rn(v.x), h1 = __float2bfloat16_rn(v.y);
    __nv_bfloat16 h2 = __float2bfloat16_rn(v.z), h3 = __float2bfloat16_rn(v.w);
    __nv_bfloat16 l0 = __float2bfloat16_rn(v.x - __bfloat162float(h0));
    __nv_bfloat16 l1 = __float2bfloat16_rn(v.y - __bfloat162float(h1));
    __nv_bfloat16 l2 = __float2bfloat16_rn(v.z - __bfloat162float(h2));
    __nv_bfloat16 l3 = __float2bfloat16_rn(v.w - __bfloat162float(h3));
    hA = __nv_bfloat162(h0, h1); hB = __nv_bfloat162(h2, h3);
    lA = __nv_bfloat162(l0, l1); lB = __nv_bfloat162(l2, l3);
}

__global__ __launch_bounds__(256)
void convert_x_kernel(const float* __restrict__ x) {
    size_t i4 = (size_t)blockIdx.x * blockDim.x + threadIdx.x;
    size_t base = i4 * 4;
    size_t t = base / D_DIM;
    int    d = (int)(base % D_DIM);
    int blk = d >> 5, pos = d & 31;
    float4 v = *reinterpret_cast<const float4*>(&x[base]);
    __nv_bfloat162 hA, hB, lA, lB;
    split4(v, hA, hB, lA, lB);
    __nv_bfloat162* ph = reinterpret_cast<__nv_bfloat162*>(&g_Ax[t * KPACK + blk * 64 + pos]);
    __nv_bfloat162* pl = reinterpret_cast<__nv_bfloat162*>(&g_Ax[t * KPACK + blk * 64 + 32 + pos]);
    ph[0] = hA; ph[1] = hB;
    pl[0] = lA; pl[1] = lB;
}

__global__ __launch_bounds__(256)
void convert_B_kernel(const float* __restrict__ Bm) {
    size_t i4 = (size_t)blockIdx.x * blockDim.x + threadIdx.x;
    size_t base = i4 * 4;
    size_t h = base / D_DIM;
    int    d = (int)(base % D_DIM);
    int blk = d >> 5, pos = d & 31;
    float4 v = *reinterpret_cast<const float4*>(&Bm[base]);
    __nv_bfloat162 hA, hB, lA, lB;
    split4(v, hA, hB, lA, lB);
    __nv_bfloat162* ph = reinterpret_cast<__nv_bfloat162*>(&g_Bx[h * KPACK + blk * 64 + pos]);
    __nv_bfloat162* pl = reinterpret_cast<__nv_bfloat162*>(&g_Bx[h * KPACK + blk * 64 + 32 + pos]);
    ph[0] = hA; ph[1] = hB;
    pl[0] = lA; pl[1] = lB;
}

// ---------------------------------------------------------------------------
// bf16 mma.sync GEMM with 3-term split:
//   u = x_hi*B_hi + x_lo*B_hi + x_hi*B_lo   (fp32 accumulate)
// Block tile 128x128, 256 threads (2x4 warps), warp tile 64x32.
// 4-stage cp.async pipeline; all LDSM of a stage hoisted ahead of MMAs.
// Epilogue fuses chunk-carry computation.
// ---------------------------------------------------------------------------
#define BM 128
#define BN 128
#define A_STAGE 16384
#define B_STAGE 16384
#define STAGE_BYTES (A_STAGE + B_STAGE)   // 32 KB
#define NPIPE 4
#define SMEM_TOTAL (NPIPE * STAGE_BYTES)  // 128 KB
#define KSTAGES (D_DIM / 32)              // 32
#define CPAD 132                          // padded fp32 row stride for carry staging

__global__ __launch_bounds__(256, 1)
void gemm_mma_kernel(const float* __restrict__ lamda) {
    extern __shared__ char smem[];
    const uint32_t sb = smem_u32(smem);
    const int tid = threadIdx.x;
    const int wid = tid >> 5, lane = tid & 31;
    const int warp_m = wid >> 2;          // 0..1
    const int warp_n = wid & 3;           // 0..3

    const int h0 = blockIdx.x * BN;
    const int t0 = blockIdx.y * BM;       // == chunk * CHUNK

    const char* Ab = reinterpret_cast<const char*>(g_Ax) + (size_t)t0 * KPACK_BYTES;
    const char* Bb = reinterpret_cast<const char*>(g_Bx) + (size_t)h0 * KPACK_BYTES;

    auto load_stage = [&](int s, int buf) {
        const uint32_t ab = sb + buf * STAGE_BYTES;
        const uint32_t bb = ab + A_STAGE;
        const size_t kbyte = (size_t)s * 128;
#pragma unroll
        for (int i = 0; i < 4; ++i) {      // A: 1024 16B chunks / 256 thr
            int j = i * 256 + tid;
            int row = j >> 3, cb = j & 7;
            uint32_t off = swz128((uint32_t)(row * 128 + cb * 16));
            CP_ASYNC16(ab + off, Ab + (size_t)row * KPACK_BYTES + kbyte + cb * 16);
        }
#pragma unroll
        for (int i = 0; i < 4; ++i) {      // B
            int j = i * 256 + tid;
            int row = j >> 3, cb = j & 7;
            uint32_t off = swz128((uint32_t)(row * 128 + cb * 16));
            CP_ASYNC16(bb + off, Bb + (size_t)row * KPACK_BYTES + kbyte + cb * 16);
        }
        CP_COMMIT();
    };

    float acc[4][4][4];
#pragma unroll
    for (int i = 0; i < 4; ++i)
#pragma unroll
        for (int j = 0; j < 4; ++j)
#pragma unroll
            for (int q = 0; q < 4; ++q) acc[i][j][q] = 0.0f;

    load_stage(0, 0);
    load_stage(1, 1);
    load_stage(2, 2);

    for (int s = 0; s < KSTAGES; ++s) {
        cp_wait<2>();            // stage s resident
        __syncthreads();         // all warps done with buffer (s+3)%4
        if (s + 3 < KSTAGES) load_stage(s + 3, (s + 3) % NPIPE);
        else CP_COMMIT();        // keep group-count invariant

        const uint32_t ab = sb + (s % NPIPE) * STAGE_BYTES;
        const uint32_t bb = ab + A_STAGE;
        const uint32_t co = (uint32_t)(lane >> 4) * 16;

        // ---- Hoist ALL fragment loads for both k16 steps of this stage ----
        uint32_t a_hi[2][4][4], a_lo[2][4][4], b_hi[2][2][4], b_lo[2][2][4];
#pragma unroll
        for (int step = 0; step < 2; ++step) {
            const uint32_t hi_base = step * 32;
            const uint32_t lo_base = 64 + step * 32;
#pragma unroll
            for (int mt = 0; mt < 4; ++mt) {
                int row = warp_m * 64 + mt * 16 + (lane & 15);
                LDSM_X4(a_hi[step][mt], ab + swz128((uint32_t)(row * 128) + hi_base + co));
                LDSM_X4(a_lo[step][mt], ab + swz128((uint32_t)(row * 128) + lo_base + co));
            }
#pragma unroll
            for (int bt = 0; bt < 2; ++bt) {
                int row = warp_n * 32 + bt * 16 + (lane & 15);
                LDSM_X4(b_hi[step][bt], bb + swz128((uint32_t)(row * 128) + hi_base + co));
                LDSM_X4(b_lo[step][bt], bb + swz128((uint32_t)(row * 128) + lo_base + co));
            }
        }
        // ---- MMAs: term-major within step, 16 independent accs ----
#pragma unroll
        for (int step = 0; step < 2; ++step) {
#pragma unroll
            for (int mt = 0; mt < 4; ++mt)
#pragma unroll
                for (int nt = 0; nt < 4; ++nt) {
                    const int bt = nt >> 1, hp = nt & 1;
                    MMA_BF16(acc[mt][nt], a_hi[step][mt], b_hi[step][bt][hp], b_hi[step][bt][2 + hp]);
                }
#pragma unroll
            for (int mt = 0; mt < 4; ++mt)
#pragma unroll
                for (int nt = 0; nt < 4; ++nt) {
                    const int bt = nt >> 1, hp = nt & 1;
                    MMA_BF16(acc[mt][nt], a_lo[step][mt], b_hi[step][bt][hp], b_hi[step][bt][2 + hp]);
                }
#pragma unroll
            for (int mt = 0; mt < 4; ++mt)
#pragma unroll
                for (int nt = 0; nt < 4; ++nt) {
                    const int bt = nt >> 1, hp = nt & 1;
                    MMA_BF16(acc[mt][nt], a_hi[step][mt], b_lo[step][bt][hp], b_lo[step][bt][2 + hp]);
                }
        }
    }

    // ---------------- Epilogue: write g_u + fused chunk-carry ----------------
    const int r = lane >> 2, c = (lane & 3) * 2;
    float* Cb = g_u + (size_t)(t0 + warp_m * 64) * H_DIM + h0 + warp_n * 32;
    __syncthreads();                       // pipeline smem now free for staging
    float* sf = reinterpret_cast<float*>(smem);   // [128][CPAD] fp32 staging

#pragma unroll
    for (int mt = 0; mt < 4; ++mt) {
#pragma unroll
        for (int nt = 0; nt < 4; ++nt) {
            float2 v0 = make_float2(acc[mt][nt][0], acc[mt][nt][1]);
            float2 v1 = make_float2(acc[mt][nt][2], acc[mt][nt][3]);
            const int tl0 = warp_m * 64 + mt * 16 + r;
            const int hl  = warp_n * 32 + nt * 8 + c;
            *reinterpret_cast<float2*>(&Cb[(size_t)(mt * 16 + r) * H_DIM + nt * 8 + c]) = v0;
            *reinterpret_cast<float2*>(&Cb[(size_t)(mt * 16 + r + 8) * H_DIM + nt * 8 + c]) = v1;
            *reinterpret_cast<float2*>(&sf[tl0 * CPAD + hl]) = v0;
            *reinterpret_cast<float2*>(&sf[(tl0 + 8) * CPAD + hl]) = v1;
        }
    }
    __syncthreads();

    if (tid < BN) {
        const float a = 1.0f / (1.0f + expf(-lamda[h0 + tid]));
        float sc = 0.0f;
#pragma unroll 8
        for (int t = 0; t < CHUNK; ++t) sc = fmaf(a, sc, sf[t * CPAD + tid]);
        g_carry[blockIdx.y * H_DIM + h0 + tid] = sc;
    }
}

// ---------------------------------------------------------------------------
// Scan pass 2: prefetch all 64 carries (independent loads, MLP), then the
// sequential 64-step register chain. Was 31.6us latency-bound; now ~3us.
// ---------------------------------------------------------------------------
__global__ __launch_bounds__(256)
void combine_kernel(const float* __restrict__ lamda) {
    const int h = blockIdx.x * blockDim.x + threadIdx.x;
    const float a = 1.0f / (1.0f + expf(-lamda[h]));
    float aC = a;
#pragma unroll
    for (int i = 0; i < 7; ++i) aC *= aC;  // a^128

    float car[NCHUNK];
#pragma unroll
    for (int c = 0; c < NCHUNK; ++c) car[c] = g_carry[c * H_DIM + h];

    float state = 0.0f;
#pragma unroll
    for (int c = 0; c < NCHUNK; ++c) {
        g_init[c * H_DIM + h] = state;
        state = fmaf(aC, state, car[c]);
    }
}

// ---------------------------------------------------------------------------
// Scan pass 3: vectorized (float4 over h), exact per-chunk rerun.
// ---------------------------------------------------------------------------
__global__ __launch_bounds__(256)
void apply_kernel(const float* __restrict__ lamda, float* __restrict__ out) {
    const int h4 = (blockIdx.x * blockDim.x + threadIdx.x) * 4;
    const int c = blockIdx.y;
    float4 lam = *reinterpret_cast<const float4*>(&lamda[h4]);
    float4 a;
    a.x = 1.0f / (1.0f + expf(-lam.x));
    a.y = 1.0f / (1.0f + expf(-lam.y));
    a.z = 1.0f / (1.0f + expf(-lam.z));
    a.w = 1.0f / (1.0f + expf(-lam.w));
    float4 s = *reinterpret_cast<const float4*>(&g_init[c * H_DIM + h4]);
    const size_t base = (size_t)c * CHUNK * H_DIM + h4;
#pragma unroll 4
    for (int t = 0; t < CHUNK; ++t) {
        float4 u = *reinterpret_cast<const float4*>(&g_u[base + (size_t)t * H_DIM]);
        s.x = fmaf(a.x, s.x, u.x);
        s.y = fmaf(a.y, s.y, u.y);
        s.z = fmaf(a.z, s.z, u.z);
        s.w = fmaf(a.w, s.w, u.w);
        *reinterpret_cast<float4*>(&out[base + (size_t)t * H_DIM]) = s;
    }
}

// ---------------------------------------------------------------------------
extern "C" void kernel_launch(void* const* d_in, const int* in_sizes, int n_in,
                              void* d_out, int out_size) {
    const float* x     = (const float*)d_in[0];  // [T, D]
    const float* lamda = (const float*)d_in[1];  // [H]
    const float* Bm    = (const float*)d_in[2];  // [H, D]
    float* out = (float*)d_out;                  // [T, H]

    convert_x_kernel<<<(T_DIM * D_DIM / 4) / 256, 256>>>(x);
    convert_B_kernel<<<(H_DIM * D_DIM / 4) / 256, 256>>>(Bm);

    cudaFuncSetAttribute(gemm_mma_kernel, cudaFuncAttributeMaxDynamicSharedMemorySize, SMEM_TOTAL);
    dim3 ggrid(H_DIM / BN, T_DIM / BM);   // (16, 64)
    gemm_mma_kernel<<<ggrid, 256, SMEM_TOTAL>>>(lamda);

    combine_kernel<<<H_DIM / 256, 256>>>(lamda);
    dim3 agrid(H_DIM / 4 / 256, NCHUNK);  // (2, 64)
    apply_kernel<<<agrid, 256>>>(lamda, out);
}

// round 6
// speedup vs baseline: 2.6567x; 1.1171x over previous
#include <cuda_runtime.h>
#include <cuda_bf16.h>
#include <math.h>
#include <stdint.h>

// Problem constants
#define T_DIM 8192
#define H_DIM 2048
#define D_DIM 1024

// Packed bf16 layout: per row of 1024 original k, 32 blocks of [hi(32) | lo(32)]
#define KPACK 2048
#define KPACK_BYTES (KPACK * 2)

#define CHUNK 128
#define NCHUNK (T_DIM / CHUNK)   // 64

// Scratch (allocation-free: __device__ globals)
__device__ float          g_u[(size_t)T_DIM * H_DIM];       // 64 MB
__device__ __nv_bfloat16  g_Ax[(size_t)T_DIM * KPACK];      // 32 MB
__device__ __nv_bfloat16  g_Bx[(size_t)H_DIM * KPACK];      // 8 MB
__device__ float          g_carry[NCHUNK * H_DIM];
__device__ float          g_init[NCHUNK * H_DIM];

// ---------------------------------------------------------------------------
// helpers
// ---------------------------------------------------------------------------
__device__ __forceinline__ uint32_t smem_u32(const void* p) {
    uint32_t a;
    asm("{ .reg .u64 t; cvta.to.shared.u64 t, %1; cvt.u32.u64 %0, t; }" : "=r"(a) : "l"(p));
    return a;
}
#define CP_ASYNC16(dst, src) \
    asm volatile("cp.async.cg.shared.global [%0], [%1], 16;" :: "r"(dst), "l"(src))
#define CP_COMMIT() asm volatile("cp.async.commit_group;" ::: "memory")
template<int N> __device__ __forceinline__ void cp_wait() {
    asm volatile("cp.async.wait_group %0;" :: "n"(N) : "memory");
}
__device__ __forceinline__ uint32_t swz128(uint32_t off) { return off ^ ((off >> 3) & 0x70); }

#define LDSM_X4(r, addr) \
    asm volatile("ldmatrix.sync.aligned.m8n8.x4.shared.b16 {%0,%1,%2,%3}, [%4];" \
                 : "=r"((r)[0]), "=r"((r)[1]), "=r"((r)[2]), "=r"((r)[3]) : "r"(addr))

#define MMA_BF16(c, a, b0, b1) \
    asm volatile("mma.sync.aligned.m16n8k16.row.col.f32.bf16.bf16.f32 " \
                 "{%0,%1,%2,%3}, {%4,%5,%6,%7}, {%8,%9}, {%0,%1,%2,%3};" \
                 : "+f"((c)[0]), "+f"((c)[1]), "+f"((c)[2]), "+f"((c)[3]) \
                 : "r"((a)[0]), "r"((a)[1]), "r"((a)[2]), "r"((a)[3]), "r"(b0), "r"(b1))

// ---------------------------------------------------------------------------
// Conversion: fp32 -> bf16 hi/lo split, packed as 32-blocks [hi32 | lo32]
// ---------------------------------------------------------------------------
__device__ __forceinline__ void split4(float4 v, __nv_bfloat162& hA, __nv_bfloat162& hB,
                                       __nv_bfloat162& lA, __nv_bfloat162& lB) {
    __nv_bfloat16 h0 = __float2bfloat16_rn(v.x), h1 = __float2bfloat16_rn(v.y);
    __nv_bfloat16 h2 = __float2bfloat16_rn(v.z), h3 = __float2bfloat16_rn(v.w);
    __nv_bfloat16 l0 = __float2bfloat16_rn(v.x - __bfloat162float(h0));
    __nv_bfloat16 l1 = __float2bfloat16_rn(v.y - __bfloat162float(h1));
    __nv_bfloat16 l2 = __float2bfloat16_rn(v.z - __bfloat162float(h2));
    __nv_bfloat16 l3 = __float2bfloat16_rn(v.w - __bfloat162float(h3));
    hA = __nv_bfloat162(h0, h1); hB = __nv_bfloat162(h2, h3);
    lA = __nv_bfloat162(l0, l1); lB = __nv_bfloat162(l2, l3);
}

__global__ __launch_bounds__(256)
void convert_x_kernel(const float* __restrict__ x) {
    size_t i4 = (size_t)blockIdx.x * blockDim.x + threadIdx.x;
    size_t base = i4 * 4;
    size_t t = base / D_DIM;
    int    d = (int)(base % D_DIM);
    int blk = d >> 5, pos = d & 31;
    float4 v = *reinterpret_cast<const float4*>(&x[base]);
    __nv_bfloat162 hA, hB, lA, lB;
    split4(v, hA, hB, lA, lB);
    __nv_bfloat162* ph = reinterpret_cast<__nv_bfloat162*>(&g_Ax[t * KPACK + blk * 64 + pos]);
    __nv_bfloat162* pl = reinterpret_cast<__nv_bfloat162*>(&g_Ax[t * KPACK + blk * 64 + 32 + pos]);
    ph[0] = hA; ph[1] = hB;
    pl[0] = lA; pl[1] = lB;
}

__global__ __launch_bounds__(256)
void convert_B_kernel(const float* __restrict__ Bm) {
    size_t i4 = (size_t)blockIdx.x * blockDim.x + threadIdx.x;
    size_t base = i4 * 4;
    size_t h = base / D_DIM;
    int    d = (int)(base % D_DIM);
    int blk = d >> 5, pos = d & 31;
    float4 v = *reinterpret_cast<const float4*>(&Bm[base]);
    __nv_bfloat162 hA, hB, lA, lB;
    split4(v, hA, hB, lA, lB);
    __nv_bfloat162* ph = reinterpret_cast<__nv_bfloat162*>(&g_Bx[h * KPACK + blk * 64 + pos]);
    __nv_bfloat162* pl = reinterpret_cast<__nv_bfloat162*>(&g_Bx[h * KPACK + blk * 64 + 32 + pos]);
    ph[0] = hA; ph[1] = hB;
    pl[0] = lA; pl[1] = lB;
}

// ---------------------------------------------------------------------------
// bf16 mma.sync GEMM with 3-term split:
//   u = x_hi*B_hi + x_lo*B_hi + x_hi*B_lo   (fp32 accumulate)
// Block tile 128x128, 256 threads (2x4 warps), warp tile 64x32.
// 3-stage cp.async pipeline, 2 CTAs/SM (4 warps/SMSP) for issue overlap.
// Register-slim mainloop (<=128 regs) to keep occupancy 2.
// ---------------------------------------------------------------------------
#define BM 128
#define BN 128
#define A_STAGE 16384
#define B_STAGE 16384
#define STAGE_BYTES (A_STAGE + B_STAGE)   // 32 KB
#define NPIPE 3
#define SMEM_TOTAL (NPIPE * STAGE_BYTES)  // 96 KB  (>= 67.6 KB carry staging)
#define KSTAGES (D_DIM / 32)              // 32
#define CPAD 132                          // padded fp32 row stride for carry staging

__global__ __launch_bounds__(256, 2)
void gemm_mma_kernel(const float* __restrict__ lamda) {
    extern __shared__ char smem[];
    const uint32_t sb = smem_u32(smem);
    const int tid = threadIdx.x;
    const int wid = tid >> 5, lane = tid & 31;
    const int warp_m = wid >> 2;          // 0..1
    const int warp_n = wid & 3;           // 0..3

    const int h0 = blockIdx.x * BN;
    const int t0 = blockIdx.y * BM;       // == chunk * CHUNK

    const char* Ab = reinterpret_cast<const char*>(g_Ax) + (size_t)t0 * KPACK_BYTES;
    const char* Bb = reinterpret_cast<const char*>(g_Bx) + (size_t)h0 * KPACK_BYTES;

    auto load_stage = [&](int s, int buf) {
        const uint32_t ab = sb + buf * STAGE_BYTES;
        const uint32_t bb = ab + A_STAGE;
        const size_t kbyte = (size_t)s * 128;
#pragma unroll
        for (int i = 0; i < 4; ++i) {      // A: 1024 16B chunks / 256 thr
            int j = i * 256 + tid;
            int row = j >> 3, cb = j & 7;
            uint32_t off = swz128((uint32_t)(row * 128 + cb * 16));
            CP_ASYNC16(ab + off, Ab + (size_t)row * KPACK_BYTES + kbyte + cb * 16);
        }
#pragma unroll
        for (int i = 0; i < 4; ++i) {      // B
            int j = i * 256 + tid;
            int row = j >> 3, cb = j & 7;
            uint32_t off = swz128((uint32_t)(row * 128 + cb * 16));
            CP_ASYNC16(bb + off, Bb + (size_t)row * KPACK_BYTES + kbyte + cb * 16);
        }
        CP_COMMIT();
    };

    float acc[4][4][4];
#pragma unroll
    for (int i = 0; i < 4; ++i)
#pragma unroll
        for (int j = 0; j < 4; ++j)
#pragma unroll
            for (int q = 0; q < 4; ++q) acc[i][j][q] = 0.0f;

    load_stage(0, 0);
    load_stage(1, 1);

    for (int s = 0; s < KSTAGES; ++s) {
        cp_wait<1>();            // stage s resident
        __syncthreads();         // all warps done with buffer (s+2)%3
        if (s + 2 < KSTAGES) load_stage(s + 2, (s + 2) % NPIPE);
        else CP_COMMIT();        // keep group-count invariant

        const uint32_t ab = sb + (s % NPIPE) * STAGE_BYTES;
        const uint32_t bb = ab + A_STAGE;
        const uint32_t co = (uint32_t)(lane >> 4) * 16;

#pragma unroll
        for (int step = 0; step < 2; ++step) {
            const uint32_t hi_base = step * 32;
            const uint32_t lo_base = 64 + step * 32;

            // b fragments for this step (4 LDSM, 32 regs)
            uint32_t b_hi[2][4], b_lo[2][4];
#pragma unroll
            for (int bt = 0; bt < 2; ++bt) {
                int row = warp_n * 32 + bt * 16 + (lane & 15);
                LDSM_X4(b_hi[bt], bb + swz128((uint32_t)(row * 128) + hi_base + co));
                LDSM_X4(b_lo[bt], bb + swz128((uint32_t)(row * 128) + lo_base + co));
            }
            // per-mt: 2 LDSM + 12 MMAs (reg-slim; cross-warp overlap hides deps)
#pragma unroll
            for (int mt = 0; mt < 4; ++mt) {
                uint32_t a_hi[4], a_lo[4];
                int row = warp_m * 64 + mt * 16 + (lane & 15);
                LDSM_X4(a_hi, ab + swz128((uint32_t)(row * 128) + hi_base + co));
                LDSM_X4(a_lo, ab + swz128((uint32_t)(row * 128) + lo_base + co));
#pragma unroll
                for (int nt = 0; nt < 4; ++nt) {
                    const int bt = nt >> 1, hp = nt & 1;
                    MMA_BF16(acc[mt][nt], a_hi, b_hi[bt][hp], b_hi[bt][2 + hp]);
                }
#pragma unroll
                for (int nt = 0; nt < 4; ++nt) {
                    const int bt = nt >> 1, hp = nt & 1;
                    MMA_BF16(acc[mt][nt], a_lo, b_hi[bt][hp], b_hi[bt][2 + hp]);
                }
#pragma unroll
                for (int nt = 0; nt < 4; ++nt) {
                    const int bt = nt >> 1, hp = nt & 1;
                    MMA_BF16(acc[mt][nt], a_hi, b_lo[bt][hp], b_lo[bt][2 + hp]);
                }
            }
        }
    }

    // ---------------- Epilogue: write g_u + fused chunk-carry ----------------
    const int r = lane >> 2, c = (lane & 3) * 2;
    float* Cb = g_u + (size_t)(t0 + warp_m * 64) * H_DIM + h0 + warp_n * 32;
    __syncthreads();                       // pipeline smem now free for staging
    float* sf = reinterpret_cast<float*>(smem);   // [128][CPAD] fp32 staging

#pragma unroll
    for (int mt = 0; mt < 4; ++mt) {
#pragma unroll
        for (int nt = 0; nt < 4; ++nt) {
            float2 v0 = make_float2(acc[mt][nt][0], acc[mt][nt][1]);
            float2 v1 = make_float2(acc[mt][nt][2], acc[mt][nt][3]);
            const int tl0 = warp_m * 64 + mt * 16 + r;
            const int hl  = warp_n * 32 + nt * 8 + c;
            *reinterpret_cast<float2*>(&Cb[(size_t)(mt * 16 + r) * H_DIM + nt * 8 + c]) = v0;
            *reinterpret_cast<float2*>(&Cb[(size_t)(mt * 16 + r + 8) * H_DIM + nt * 8 + c]) = v1;
            *reinterpret_cast<float2*>(&sf[tl0 * CPAD + hl]) = v0;
            *reinterpret_cast<float2*>(&sf[(tl0 + 8) * CPAD + hl]) = v1;
        }
    }
    __syncthreads();

    if (tid < BN) {
        const float a = 1.0f / (1.0f + expf(-lamda[h0 + tid]));
        float sc = 0.0f;
#pragma unroll 8
        for (int t = 0; t < CHUNK; ++t) sc = fmaf(a, sc, sf[t * CPAD + tid]);
        g_carry[blockIdx.y * H_DIM + h0 + tid] = sc;
    }
}

// ---------------------------------------------------------------------------
// Scan pass 2: prefetch all 64 carries (MLP), then register chain.
// ---------------------------------------------------------------------------
__global__ __launch_bounds__(256)
void combine_kernel(const float* __restrict__ lamda) {
    const int h = blockIdx.x * blockDim.x + threadIdx.x;
    const float a = 1.0f / (1.0f + expf(-lamda[h]));
    float aC = a;
#pragma unroll
    for (int i = 0; i < 7; ++i) aC *= aC;  // a^128

    float car[NCHUNK];
#pragma unroll
    for (int c = 0; c < NCHUNK; ++c) car[c] = g_carry[c * H_DIM + h];

    float state = 0.0f;
#pragma unroll
    for (int c = 0; c < NCHUNK; ++c) {
        g_init[c * H_DIM + h] = state;
        state = fmaf(aC, state, car[c]);
    }
}

// ---------------------------------------------------------------------------
// Scan pass 3: vectorized (float4 over h), exact per-chunk rerun.
// ---------------------------------------------------------------------------
__global__ __launch_bounds__(256)
void apply_kernel(const float* __restrict__ lamda, float* __restrict__ out) {
    const int h4 = (blockIdx.x * blockDim.x + threadIdx.x) * 4;
    const int c = blockIdx.y;
    float4 lam = *reinterpret_cast<const float4*>(&lamda[h4]);
    float4 a;
    a.x = 1.0f / (1.0f + expf(-lam.x));
    a.y = 1.0f / (1.0f + expf(-lam.y));
    a.z = 1.0f / (1.0f + expf(-lam.z));
    a.w = 1.0f / (1.0f + expf(-lam.w));
    float4 s = *reinterpret_cast<const float4*>(&g_init[c * H_DIM + h4]);
    const size_t base = (size_t)c * CHUNK * H_DIM + h4;
#pragma unroll 4
    for (int t = 0; t < CHUNK; ++t) {
        float4 u = *reinterpret_cast<const float4*>(&g_u[base + (size_t)t * H_DIM]);
        s.x = fmaf(a.x, s.x, u.x);
        s.y = fmaf(a.y, s.y, u.y);
        s.z = fmaf(a.z, s.z, u.z);
        s.w = fmaf(a.w, s.w, u.w);
        *reinterpret_cast<float4*>(&out[base + (size_t)t * H_DIM]) = s;
    }
}

// ---------------------------------------------------------------------------
extern "C" void kernel_launch(void* const* d_in, const int* in_sizes, int n_in,
                              void* d_out, int out_size) {
    const float* x     = (const float*)d_in[0];  // [T, D]
    const float* lamda = (const float*)d_in[1];  // [H]
    const float* Bm    = (const float*)d_in[2];  // [H, D]
    float* out = (float*)d_out;                  // [T, H]

    convert_x_kernel<<<(T_DIM * D_DIM / 4) / 256, 256>>>(x);
    convert_B_kernel<<<(H_DIM * D_DIM / 4) / 256, 256>>>(Bm);

    cudaFuncSetAttribute(gemm_mma_kernel, cudaFuncAttributeMaxDynamicSharedMemorySize, SMEM_TOTAL);
    dim3 ggrid(H_DIM / BN, T_DIM / BM);   // (16, 64)
    gemm_mma_kernel<<<ggrid, 256, SMEM_TOTAL>>>(lamda);

    combine_kernel<<<H_DIM / 256, 256>>>(lamda);
    dim3 agrid(H_DIM / 4 / 256, NCHUNK);  // (2, 64)
    apply_kernel<<<agrid, 256>>>(lamda, out);
}

// round 7
// speedup vs baseline: 2.8206x; 1.0617x over previous
#include <cuda_runtime.h>
#include <cuda.h>
#include <cuda_bf16.h>
#include <math.h>
#include <stdint.h>

// Problem constants
#define T_DIM 8192
#define H_DIM 2048
#define D_DIM 1024

// Packed bf16 layout: per row of 1024 original k, 32 blocks of [hi(32) | lo(32)]
#define KPACK 2048
#define KPACK_BYTES (KPACK * 2)   // 4096

#define CHUNK 128
#define NCHUNK (T_DIM / CHUNK)   // 64

// Scratch (allocation-free: __device__ globals)
__device__ float          g_u[(size_t)T_DIM * H_DIM];       // 64 MB
__device__ __nv_bfloat16  g_Ax[(size_t)T_DIM * KPACK];      // 32 MB
__device__ __nv_bfloat16  g_Bx[(size_t)H_DIM * KPACK];      // 8 MB
__device__ float          g_carry[NCHUNK * H_DIM];
__device__ float          g_init[NCHUNK * H_DIM];

// ---------------------------------------------------------------------------
// helpers
// ---------------------------------------------------------------------------
__device__ __forceinline__ uint32_t smem_u32(const void* p) {
    uint32_t a;
    asm("{ .reg .u64 t; cvta.to.shared.u64 t, %1; cvt.u32.u64 %0, t; }" : "=r"(a) : "l"(p));
    return a;
}
__device__ __forceinline__ uint32_t swz128(uint32_t off) { return off ^ ((off >> 3) & 0x70); }

#define MBAR_INIT(addr, cnt) \
    asm volatile("mbarrier.init.shared.b64 [%0], %1;" :: "r"(addr), "r"(cnt) : "memory")
#define MBAR_EXPECT_TX(addr, bytes) \
    asm volatile("mbarrier.arrive.expect_tx.shared.b64 _, [%0], %1;" :: "r"(addr), "r"(bytes) : "memory")

__device__ __forceinline__ void mbar_wait(uint32_t mbar, uint32_t parity) {
    uint32_t done;
    asm volatile(
        "{\n\t.reg .pred p;\n\t"
        "mbarrier.try_wait.parity.acquire.cta.shared::cta.b64 p, [%1], %2;\n\t"
        "selp.b32 %0, 1, 0, p;\n\t}"
        : "=r"(done) : "r"(mbar), "r"(parity) : "memory");
    if (!done) {
        asm volatile(
            "{\n\t.reg .pred P1;\n\t"
            "W_%=:\n\t"
            "mbarrier.try_wait.parity.acquire.cta.shared::cta.b64 P1, [%0], %1, 0x989680;\n\t"
            "@P1 bra.uni D_%=;\n\t"
            "bra.uni W_%=;\n\t"
            "D_%=:\n\t}"
            :: "r"(mbar), "r"(parity) : "memory");
    }
}

#define TMA_LOAD_2D(dst, tmap, cx, cy, mbar) \
    asm volatile("cp.async.bulk.tensor.2d.shared::cluster.global.tile.mbarrier::complete_tx::bytes " \
                 "[%0], [%1, {%2, %3}], [%4];" \
                 :: "r"(dst), "l"(tmap), "r"(cx), "r"(cy), "r"(mbar) : "memory")

#define LDSM_X4(r, addr) \
    asm volatile("ldmatrix.sync.aligned.m8n8.x4.shared.b16 {%0,%1,%2,%3}, [%4];" \
                 : "=r"((r)[0]), "=r"((r)[1]), "=r"((r)[2]), "=r"((r)[3]) : "r"(addr))

#define MMA_BF16(c, a, b0, b1) \
    asm volatile("mma.sync.aligned.m16n8k16.row.col.f32.bf16.bf16.f32 " \
                 "{%0,%1,%2,%3}, {%4,%5,%6,%7}, {%8,%9}, {%0,%1,%2,%3};" \
                 : "+f"((c)[0]), "+f"((c)[1]), "+f"((c)[2]), "+f"((c)[3]) \
                 : "r"((a)[0]), "r"((a)[1]), "r"((a)[2]), "r"((a)[3]), "r"(b0), "r"(b1))

// ---------------------------------------------------------------------------
// Conversion: fp32 -> bf16 hi/lo split, packed as 32-blocks [hi32 | lo32]
// ---------------------------------------------------------------------------
__device__ __forceinline__ void split4(float4 v, __nv_bfloat162& hA, __nv_bfloat162& hB,
                                       __nv_bfloat162& lA, __nv_bfloat162& lB) {
    __nv_bfloat16 h0 = __float2bfloat16_rn(v.x), h1 = __float2bfloat16_rn(v.y);
    __nv_bfloat16 h2 = __float2bfloat16_rn(v.z), h3 = __float2bfloat16_rn(v.w);
    __nv_bfloat16 l0 = __float2bfloat16_rn(v.x - __bfloat162float(h0));
    __nv_bfloat16 l1 = __float2bfloat16_rn(v.y - __bfloat162float(h1));
    __nv_bfloat16 l2 = __float2bfloat16_rn(v.z - __bfloat162float(h2));
    __nv_bfloat16 l3 = __float2bfloat16_rn(v.w - __bfloat162float(h3));
    hA = __nv_bfloat162(h0, h1); hB = __nv_bfloat162(h2, h3);
    lA = __nv_bfloat162(l0, l1); lB = __nv_bfloat162(l2, l3);
}

__global__ __launch_bounds__(256)
void convert_x_kernel(const float* __restrict__ x) {
    size_t i4 = (size_t)blockIdx.x * blockDim.x + threadIdx.x;
    size_t base = i4 * 4;
    size_t t = base / D_DIM;
    int    d = (int)(base % D_DIM);
    int blk = d >> 5, pos = d & 31;
    float4 v = *reinterpret_cast<const float4*>(&x[base]);
    __nv_bfloat162 hA, hB, lA, lB;
    split4(v, hA, hB, lA, lB);
    __nv_bfloat162* ph = reinterpret_cast<__nv_bfloat162*>(&g_Ax[t * KPACK + blk * 64 + pos]);
    __nv_bfloat162* pl = reinterpret_cast<__nv_bfloat162*>(&g_Ax[t * KPACK + blk * 64 + 32 + pos]);
    ph[0] = hA; ph[1] = hB;
    pl[0] = lA; pl[1] = lB;
}

__global__ __launch_bounds__(256)
void convert_B_kernel(const float* __restrict__ Bm) {
    size_t i4 = (size_t)blockIdx.x * blockDim.x + threadIdx.x;
    size_t base = i4 * 4;
    size_t h = base / D_DIM;
    int    d = (int)(base % D_DIM);
    int blk = d >> 5, pos = d & 31;
    float4 v = *reinterpret_cast<const float4*>(&Bm[base]);
    __nv_bfloat162 hA, hB, lA, lB;
    split4(v, hA, hB, lA, lB);
    __nv_bfloat162* ph = reinterpret_cast<__nv_bfloat162*>(&g_Bx[h * KPACK + blk * 64 + pos]);
    __nv_bfloat162* pl = reinterpret_cast<__nv_bfloat162*>(&g_Bx[h * KPACK + blk * 64 + 32 + pos]);
    ph[0] = hA; ph[1] = hB;
    pl[0] = lA; pl[1] = lB;
}

// ---------------------------------------------------------------------------
// bf16 mma.sync GEMM with 3-term split, TMA-fed pipeline:
//   u = x_hi*B_hi + x_lo*B_hi + x_hi*B_lo   (fp32 accumulate)
// Block tile 128x128, 256 threads (2x4 warps), warp tile 64x32.
// 3-stage TMA pipeline (mbarrier phase-tracked), 2 CTAs/SM.
// Epilogue fuses chunk-carry computation.
// ---------------------------------------------------------------------------
#define BM 128
#define BN 128
#define A_STAGE 16384
#define B_STAGE 16384
#define STAGE_BYTES (A_STAGE + B_STAGE)   // 32 KB
#define NPIPE 3
#define SMEM_BUFS 1024                    // mbarriers + pad, keeps stages 1KB-aligned
#define SMEM_TOTAL (SMEM_BUFS + NPIPE * STAGE_BYTES)  // 99328
#define KSTAGES (D_DIM / 32)              // 32
#define CPAD 132                          // padded fp32 row stride for carry staging

__global__ __launch_bounds__(256, 2)
void gemm_mma_kernel(const __grid_constant__ CUtensorMap tma_a,
                     const __grid_constant__ CUtensorMap tma_b,
                     const float* __restrict__ lamda) {
    extern __shared__ char smem[];
    const uint32_t sb = smem_u32(smem);
    const int tid = threadIdx.x;
    const int wid = tid >> 5, lane = tid & 31;
    const int warp_m = wid >> 2;          // 0..1
    const int warp_n = wid & 3;           // 0..3

    const int h0 = blockIdx.x * BN;
    const int t0 = blockIdx.y * BM;       // == chunk * CHUNK

    // mbarriers: one per pipeline slot
    if (tid == 0) {
#pragma unroll
        for (int i = 0; i < NPIPE; ++i) MBAR_INIT(sb + i * 8, 1);
    }
    __syncthreads();

    auto issue_stage = [&](int s) {
        const int slot = s % NPIPE;
        const uint32_t mbar = sb + slot * 8;
        const uint32_t buf = sb + SMEM_BUFS + slot * STAGE_BYTES;
        MBAR_EXPECT_TX(mbar, STAGE_BYTES);
        TMA_LOAD_2D(buf,           &tma_a, s * 128, t0, mbar);
        TMA_LOAD_2D(buf + A_STAGE, &tma_b, s * 128, h0, mbar);
    };

    float acc[4][4][4];
#pragma unroll
    for (int i = 0; i < 4; ++i)
#pragma unroll
        for (int j = 0; j < 4; ++j)
#pragma unroll
            for (int q = 0; q < 4; ++q) acc[i][j][q] = 0.0f;

    if (tid == 0) { issue_stage(0); issue_stage(1); }

    for (int s = 0; s < KSTAGES; ++s) {
        __syncthreads();                 // consumers of slot (s+2)%3 (iter s-1) done
        if (tid == 0 && s + 2 < KSTAGES) issue_stage(s + 2);
        mbar_wait(sb + (s % NPIPE) * 8, (uint32_t)((s / NPIPE) & 1));

        const uint32_t ab = sb + SMEM_BUFS + (s % NPIPE) * STAGE_BYTES;
        const uint32_t bb = ab + A_STAGE;
        const uint32_t co = (uint32_t)(lane >> 4) * 16;

#pragma unroll
        for (int step = 0; step < 2; ++step) {
            const uint32_t hi_base = step * 32;
            const uint32_t lo_base = 64 + step * 32;

            uint32_t b_hi[2][4], b_lo[2][4];
#pragma unroll
            for (int bt = 0; bt < 2; ++bt) {
                int row = warp_n * 32 + bt * 16 + (lane & 15);
                LDSM_X4(b_hi[bt], bb + swz128((uint32_t)(row * 128) + hi_base + co));
                LDSM_X4(b_lo[bt], bb + swz128((uint32_t)(row * 128) + lo_base + co));
            }
#pragma unroll
            for (int mt = 0; mt < 4; ++mt) {
                uint32_t a_hi[4], a_lo[4];
                int row = warp_m * 64 + mt * 16 + (lane & 15);
                LDSM_X4(a_hi, ab + swz128((uint32_t)(row * 128) + hi_base + co));
                LDSM_X4(a_lo, ab + swz128((uint32_t)(row * 128) + lo_base + co));
#pragma unroll
                for (int nt = 0; nt < 4; ++nt) {
                    const int bt = nt >> 1, hp = nt & 1;
                    MMA_BF16(acc[mt][nt], a_hi, b_hi[bt][hp], b_hi[bt][2 + hp]);
                }
#pragma unroll
                for (int nt = 0; nt < 4; ++nt) {
                    const int bt = nt >> 1, hp = nt & 1;
                    MMA_BF16(acc[mt][nt], a_lo, b_hi[bt][hp], b_hi[bt][2 + hp]);
                }
#pragma unroll
                for (int nt = 0; nt < 4; ++nt) {
                    const int bt = nt >> 1, hp = nt & 1;
                    MMA_BF16(acc[mt][nt], a_hi, b_lo[bt][hp], b_lo[bt][2 + hp]);
                }
            }
        }
    }

    // ---------------- Epilogue: write g_u + fused chunk-carry ----------------
    const int r = lane >> 2, c = (lane & 3) * 2;
    float* Cb = g_u + (size_t)(t0 + warp_m * 64) * H_DIM + h0 + warp_n * 32;
    __syncthreads();                       // pipeline smem now free for staging
    float* sf = reinterpret_cast<float*>(smem + SMEM_BUFS);   // [128][CPAD] staging

#pragma unroll
    for (int mt = 0; mt < 4; ++mt) {
#pragma unroll
        for (int nt = 0; nt < 4; ++nt) {
            float2 v0 = make_float2(acc[mt][nt][0], acc[mt][nt][1]);
            float2 v1 = make_float2(acc[mt][nt][2], acc[mt][nt][3]);
            const int tl0 = warp_m * 64 + mt * 16 + r;
            const int hl  = warp_n * 32 + nt * 8 + c;
            *reinterpret_cast<float2*>(&Cb[(size_t)(mt * 16 + r) * H_DIM + nt * 8 + c]) = v0;
            *reinterpret_cast<float2*>(&Cb[(size_t)(mt * 16 + r + 8) * H_DIM + nt * 8 + c]) = v1;
            *reinterpret_cast<float2*>(&sf[tl0 * CPAD + hl]) = v0;
            *reinterpret_cast<float2*>(&sf[(tl0 + 8) * CPAD + hl]) = v1;
        }
    }
    __syncthreads();

    if (tid < BN) {
        const float a = 1.0f / (1.0f + expf(-lamda[h0 + tid]));
        float sc = 0.0f;
#pragma unroll 8
        for (int t = 0; t < CHUNK; ++t) sc = fmaf(a, sc, sf[t * CPAD + tid]);
        g_carry[blockIdx.y * H_DIM + h0 + tid] = sc;
    }
}

// ---------------------------------------------------------------------------
// Scan pass 2: prefetch all 64 carries (MLP), then register chain.
// ---------------------------------------------------------------------------
__global__ __launch_bounds__(256)
void combine_kernel(const float* __restrict__ lamda) {
    const int h = blockIdx.x * blockDim.x + threadIdx.x;
    const float a = 1.0f / (1.0f + expf(-lamda[h]));
    float aC = a;
#pragma unroll
    for (int i = 0; i < 7; ++i) aC *= aC;  // a^128

    float car[NCHUNK];
#pragma unroll
    for (int c = 0; c < NCHUNK; ++c) car[c] = g_carry[c * H_DIM + h];

    float state = 0.0f;
#pragma unroll
    for (int c = 0; c < NCHUNK; ++c) {
        g_init[c * H_DIM + h] = state;
        state = fmaf(aC, state, car[c]);
    }
}

// ---------------------------------------------------------------------------
// Scan pass 3: vectorized (float4 over h), exact per-chunk rerun.
// ---------------------------------------------------------------------------
__global__ __launch_bounds__(256)
void apply_kernel(const float* __restrict__ lamda, float* __restrict__ out) {
    const int h4 = (blockIdx.x * blockDim.x + threadIdx.x) * 4;
    const int c = blockIdx.y;
    float4 lam = *reinterpret_cast<const float4*>(&lamda[h4]);
    float4 a;
    a.x = 1.0f / (1.0f + expf(-lam.x));
    a.y = 1.0f / (1.0f + expf(-lam.y));
    a.z = 1.0f / (1.0f + expf(-lam.z));
    a.w = 1.0f / (1.0f + expf(-lam.w));
    float4 s = *reinterpret_cast<const float4*>(&g_init[c * H_DIM + h4]);
    const size_t base = (size_t)c * CHUNK * H_DIM + h4;
#pragma unroll 4
    for (int t = 0; t < CHUNK; ++t) {
        float4 u = *reinterpret_cast<const float4*>(&g_u[base + (size_t)t * H_DIM]);
        s.x = fmaf(a.x, s.x, u.x);
        s.y = fmaf(a.y, s.y, u.y);
        s.z = fmaf(a.z, s.z, u.z);
        s.w = fmaf(a.w, s.w, u.w);
        *reinterpret_cast<float4*>(&out[base + (size_t)t * H_DIM]) = s;
    }
}

// ---------------------------------------------------------------------------
// Host: TMA descriptor creation via runtime entry point (no -lcuda needed)
// ---------------------------------------------------------------------------
typedef CUresult (*PFN_tmapEncode)(
    CUtensorMap*, CUtensorMapDataType, cuuint32_t, void*,
    const cuuint64_t*, const cuuint64_t*, const cuuint32_t*, const cuuint32_t*,
    CUtensorMapInterleave, CUtensorMapSwizzle, CUtensorMapL2promotion,
    CUtensorMapFloatOOBfill);

extern "C" void kernel_launch(void* const* d_in, const int* in_sizes, int n_in,
                              void* d_out, int out_size) {
    const float* x     = (const float*)d_in[0];  // [T, D]
    const float* lamda = (const float*)d_in[1];  // [H]
    const float* Bm    = (const float*)d_in[2];  // [H, D]
    float* out = (float*)d_out;                  // [T, H]

    // Build TMA descriptors (deterministic; pure host work, capture-safe)
    void* pfn = nullptr;
    cudaDriverEntryPointQueryResult qres;
    cudaGetDriverEntryPoint("cuTensorMapEncodeTiled", &pfn, cudaEnableDefault, &qres);
    PFN_tmapEncode encode = (PFN_tmapEncode)pfn;

    void *ax_ptr = nullptr, *bx_ptr = nullptr;
    cudaGetSymbolAddress(&ax_ptr, g_Ax);
    cudaGetSymbolAddress(&bx_ptr, g_Bx);

    CUtensorMap tma_a, tma_b;
    {
        cuuint64_t dims[2]  = {KPACK_BYTES, T_DIM};     // bytes per row, rows
        cuuint64_t strides[1] = {KPACK_BYTES};
        cuuint32_t box[2]   = {128, BM};
        cuuint32_t es[2]    = {1, 1};
        encode(&tma_a, CU_TENSOR_MAP_DATA_TYPE_UINT8, 2, ax_ptr,
               dims, strides, box, es,
               CU_TENSOR_MAP_INTERLEAVE_NONE, CU_TENSOR_MAP_SWIZZLE_128B,
               CU_TENSOR_MAP_L2_PROMOTION_L2_128B, CU_TENSOR_MAP_FLOAT_OOB_FILL_NONE);
    }
    {
        cuuint64_t dims[2]  = {KPACK_BYTES, H_DIM};
        cuuint64_t strides[1] = {KPACK_BYTES};
        cuuint32_t box[2]   = {128, BN};
        cuuint32_t es[2]    = {1, 1};
        encode(&tma_b, CU_TENSOR_MAP_DATA_TYPE_UINT8, 2, bx_ptr,
               dims, strides, box, es,
               CU_TENSOR_MAP_INTERLEAVE_NONE, CU_TENSOR_MAP_SWIZZLE_128B,
               CU_TENSOR_MAP_L2_PROMOTION_L2_128B, CU_TENSOR_MAP_FLOAT_OOB_FILL_NONE);
    }

    convert_x_kernel<<<(T_DIM * D_DIM / 4) / 256, 256>>>(x);
    convert_B_kernel<<<(H_DIM * D_DIM / 4) / 256, 256>>>(Bm);

    cudaFuncSetAttribute(gemm_mma_kernel, cudaFuncAttributeMaxDynamicSharedMemorySize, SMEM_TOTAL);
    dim3 ggrid(H_DIM / BN, T_DIM / BM);   // (16, 64)
    gemm_mma_kernel<<<ggrid, 256, SMEM_TOTAL>>>(tma_a, tma_b, lamda);

    combine_kernel<<<H_DIM / 256, 256>>>(lamda);
    dim3 agrid(H_DIM / 4 / 256, NCHUNK);  // (2, 64)
    apply_kernel<<<agrid, 256>>>(lamda, out);
}

// round 8
// speedup vs baseline: 3.6453x; 1.2924x over previous
#include <cuda_runtime.h>
#include <cuda.h>
#include <cuda_fp16.h>
#include <math.h>
#include <stdint.h>

// Problem constants
#define T_DIM 8192
#define H_DIM 2048
#define D_DIM 1024

// A (x) packed fp16 hi/lo: per 32-orig-k block [hi32 | lo32] -> row 4096B
#define KPACK_A 2048
#define KPACK_A_BYTES (KPACK_A * 2)   // 4096
// B single fp16: row 2048B
#define KB_BYTES (D_DIM * 2)          // 2048

#define CHUNK 128
#define NCHUNK (T_DIM / CHUNK)   // 64

// Scratch (allocation-free: __device__ globals)
__device__ float   g_u[(size_t)T_DIM * H_DIM];        // 64 MB
__device__ __half  g_Axh[(size_t)T_DIM * KPACK_A];    // 32 MB
__device__ __half  g_Bh[(size_t)H_DIM * D_DIM];       // 4 MB
__device__ float   g_carry[NCHUNK * H_DIM];
__device__ float   g_init[NCHUNK * H_DIM];

// ---------------------------------------------------------------------------
// helpers
// ---------------------------------------------------------------------------
__device__ __forceinline__ uint32_t smem_u32(const void* p) {
    uint32_t a;
    asm("{ .reg .u64 t; cvta.to.shared.u64 t, %1; cvt.u32.u64 %0, t; }" : "=r"(a) : "l"(p));
    return a;
}
__device__ __forceinline__ uint32_t swz128(uint32_t off) { return off ^ ((off >> 3) & 0x70); }

#define MBAR_INIT(addr, cnt) \
    asm volatile("mbarrier.init.shared.b64 [%0], %1;" :: "r"(addr), "r"(cnt) : "memory")
#define MBAR_EXPECT_TX(addr, bytes) \
    asm volatile("mbarrier.arrive.expect_tx.shared.b64 _, [%0], %1;" :: "r"(addr), "r"(bytes) : "memory")

__device__ __forceinline__ void mbar_wait(uint32_t mbar, uint32_t parity) {
    uint32_t done;
    asm volatile(
        "{\n\t.reg .pred p;\n\t"
        "mbarrier.try_wait.parity.acquire.cta.shared::cta.b64 p, [%1], %2;\n\t"
        "selp.b32 %0, 1, 0, p;\n\t}"
        : "=r"(done) : "r"(mbar), "r"(parity) : "memory");
    if (!done) {
        asm volatile(
            "{\n\t.reg .pred P1;\n\t"
            "W_%=:\n\t"
            "mbarrier.try_wait.parity.acquire.cta.shared::cta.b64 P1, [%0], %1, 0x989680;\n\t"
            "@P1 bra.uni D_%=;\n\t"
            "bra.uni W_%=;\n\t"
            "D_%=:\n\t}"
            :: "r"(mbar), "r"(parity) : "memory");
    }
}

#define TMA_LOAD_2D(dst, tmap, cx, cy, mbar) \
    asm volatile("cp.async.bulk.tensor.2d.shared::cluster.global.tile.mbarrier::complete_tx::bytes " \
                 "[%0], [%1, {%2, %3}], [%4];" \
                 :: "r"(dst), "l"(tmap), "r"(cx), "r"(cy), "r"(mbar) : "memory")

#define LDSM_X4(r, addr) \
    asm volatile("ldmatrix.sync.aligned.m8n8.x4.shared.b16 {%0,%1,%2,%3}, [%4];" \
                 : "=r"((r)[0]), "=r"((r)[1]), "=r"((r)[2]), "=r"((r)[3]) : "r"(addr))

#define MMA_F16(c, a, b0, b1) \
    asm volatile("mma.sync.aligned.m16n8k16.row.col.f32.f16.f16.f32 " \
                 "{%0,%1,%2,%3}, {%4,%5,%6,%7}, {%8,%9}, {%0,%1,%2,%3};" \
                 : "+f"((c)[0]), "+f"((c)[1]), "+f"((c)[2]), "+f"((c)[3]) \
                 : "r"((a)[0]), "r"((a)[1]), "r"((a)[2]), "r"((a)[3]), "r"(b0), "r"(b1))

// ---------------------------------------------------------------------------
// Conversions
// ---------------------------------------------------------------------------
__global__ __launch_bounds__(256)
void convert_x_kernel(const float* __restrict__ x) {
    size_t i4 = (size_t)blockIdx.x * blockDim.x + threadIdx.x;
    size_t base = i4 * 4;
    size_t t = base / D_DIM;
    int    d = (int)(base % D_DIM);
    int blk = d >> 5, pos = d & 31;
    float4 v = *reinterpret_cast<const float4*>(&x[base]);
    __half h0 = __float2half_rn(v.x), h1 = __float2half_rn(v.y);
    __half h2 = __float2half_rn(v.z), h3 = __float2half_rn(v.w);
    __half l0 = __float2half_rn(v.x - __half2float(h0));
    __half l1 = __float2half_rn(v.y - __half2float(h1));
    __half l2 = __float2half_rn(v.z - __half2float(h2));
    __half l3 = __float2half_rn(v.w - __half2float(h3));
    __half2 hA = __halves2half2(h0, h1), hB = __halves2half2(h2, h3);
    __half2 lA = __halves2half2(l0, l1), lB = __halves2half2(l2, l3);
    __half2* ph = reinterpret_cast<__half2*>(&g_Axh[t * KPACK_A + blk * 64 + pos]);
    __half2* pl = reinterpret_cast<__half2*>(&g_Axh[t * KPACK_A + blk * 64 + 32 + pos]);
    ph[0] = hA; ph[1] = hB;
    pl[0] = lA; pl[1] = lB;
}

__global__ __launch_bounds__(256)
void convert_B_kernel(const float* __restrict__ Bm) {
    size_t i4 = (size_t)blockIdx.x * blockDim.x + threadIdx.x;
    size_t base = i4 * 4;
    float4 v = *reinterpret_cast<const float4*>(&Bm[base]);
    __half2 a = __halves2half2(__float2half_rn(v.x), __float2half_rn(v.y));
    __half2 b = __halves2half2(__float2half_rn(v.z), __float2half_rn(v.w));
    __half2* p = reinterpret_cast<__half2*>(&g_Bh[base]);
    p[0] = a; p[1] = b;
}

// ---------------------------------------------------------------------------
// fp16 mma.sync GEMM, 2-term split:
//   u = x_hi*B + x_lo*B   (fp32 accumulate; B rounded to fp16)
// Block tile 128x128, 256 threads (2x4 warps), warp tile 64x32.
// 2-stage TMA pipeline (stage = 64 orig k), 2 CTAs/SM.
// Epilogue fuses chunk-carry computation.
// ---------------------------------------------------------------------------
#define BM 128
#define BN 128
#define A_SUB 16384                        // one 128B x 128-row box
#define STAGE_BYTES (3 * A_SUB)            // A0 + A1 + B = 48 KB
#define NPIPE 2
#define SMEM_BUFS 1024
#define SMEM_TOTAL (SMEM_BUFS + NPIPE * STAGE_BYTES)  // 99328
#define KSTAGES (D_DIM / 64)               // 16 (stage = 64 orig k)
#define CPAD 132                           // padded fp32 row stride for carry staging

__global__ __launch_bounds__(256, 2)
void gemm_mma_kernel(const __grid_constant__ CUtensorMap tma_a,
                     const __grid_constant__ CUtensorMap tma_b,
                     const float* __restrict__ lamda) {
    extern __shared__ __align__(1024) char smem[];
    const uint32_t sb = smem_u32(smem);
    const int tid = threadIdx.x;
    const int wid = tid >> 5, lane = tid & 31;
    const int warp_m = wid >> 2;          // 0..1
    const int warp_n = wid & 3;           // 0..3

    const int h0 = blockIdx.x * BN;
    const int t0 = blockIdx.y * BM;       // == chunk * CHUNK

    if (tid == 0) {
#pragma unroll
        for (int i = 0; i < NPIPE; ++i) MBAR_INIT(sb + i * 8, 1);
    }
    __syncthreads();

    auto issue_stage = [&](int s) {
        const int slot = s & 1;
        const uint32_t mbar = sb + slot * 8;
        const uint32_t buf = sb + SMEM_BUFS + slot * STAGE_BYTES;
        MBAR_EXPECT_TX(mbar, STAGE_BYTES);
        TMA_LOAD_2D(buf,             &tma_a, s * 256,       t0, mbar);  // block 2s
        TMA_LOAD_2D(buf + A_SUB,     &tma_a, s * 256 + 128, t0, mbar);  // block 2s+1
        TMA_LOAD_2D(buf + 2 * A_SUB, &tma_b, s * 128,       h0, mbar);  // 64 k of B
    };

    float acc[4][4][4];
#pragma unroll
    for (int i = 0; i < 4; ++i)
#pragma unroll
        for (int j = 0; j < 4; ++j)
#pragma unroll
            for (int q = 0; q < 4; ++q) acc[i][j][q] = 0.0f;

    if (tid == 0) { issue_stage(0); issue_stage(1); }

    for (int s = 0; s < KSTAGES; ++s) {
        mbar_wait(sb + (s & 1) * 8, (uint32_t)((s >> 1) & 1));

        const uint32_t buf = sb + SMEM_BUFS + (s & 1) * STAGE_BYTES;
        const uint32_t bb = buf + 2 * A_SUB;
        const uint32_t co = (uint32_t)(lane >> 4) * 16;

#pragma unroll
        for (int g = 0; g < 4; ++g) {            // four k16 steps per stage
            const uint32_t ab = buf + (g >> 1) * A_SUB;   // A0 for g<2, A1 else
            const uint32_t hi_base = (g & 1) * 32;
            const uint32_t lo_base = 64 + (g & 1) * 32;
            const uint32_t b_base  = g * 32;

            uint32_t b_f[2][4];
#pragma unroll
            for (int bt = 0; bt < 2; ++bt) {
                int row = warp_n * 32 + bt * 16 + (lane & 15);
                LDSM_X4(b_f[bt], bb + swz128((uint32_t)(row * 128) + b_base + co));
            }
#pragma unroll
            for (int mt = 0; mt < 4; ++mt) {
                uint32_t a_hi[4], a_lo[4];
                int row = warp_m * 64 + mt * 16 + (lane & 15);
                LDSM_X4(a_hi, ab + swz128((uint32_t)(row * 128) + hi_base + co));
                LDSM_X4(a_lo, ab + swz128((uint32_t)(row * 128) + lo_base + co));
#pragma unroll
                for (int nt = 0; nt < 4; ++nt) {
                    const int bt = nt >> 1, hp = nt & 1;
                    MMA_F16(acc[mt][nt], a_hi, b_f[bt][hp], b_f[bt][2 + hp]);
                }
#pragma unroll
                for (int nt = 0; nt < 4; ++nt) {
                    const int bt = nt >> 1, hp = nt & 1;
                    MMA_F16(acc[mt][nt], a_lo, b_f[bt][hp], b_f[bt][2 + hp]);
                }
            }
        }

        __syncthreads();                 // all warps done with this slot
        if (tid == 0 && s + 2 < KSTAGES) issue_stage(s + 2);
    }

    // ---------------- Epilogue: write g_u + fused chunk-carry ----------------
    const int r = lane >> 2, c = (lane & 3) * 2;
    float* Cb = g_u + (size_t)(t0 + warp_m * 64) * H_DIM + h0 + warp_n * 32;
    float* sf = reinterpret_cast<float*>(smem + SMEM_BUFS);   // [128][CPAD] staging

#pragma unroll
    for (int mt = 0; mt < 4; ++mt) {
#pragma unroll
        for (int nt = 0; nt < 4; ++nt) {
            float2 v0 = make_float2(acc[mt][nt][0], acc[mt][nt][1]);
            float2 v1 = make_float2(acc[mt][nt][2], acc[mt][nt][3]);
            const int tl0 = warp_m * 64 + mt * 16 + r;
            const int hl  = warp_n * 32 + nt * 8 + c;
            *reinterpret_cast<float2*>(&Cb[(size_t)(mt * 16 + r) * H_DIM + nt * 8 + c]) = v0;
            *reinterpret_cast<float2*>(&Cb[(size_t)(mt * 16 + r + 8) * H_DIM + nt * 8 + c]) = v1;
            *reinterpret_cast<float2*>(&sf[tl0 * CPAD + hl]) = v0;
            *reinterpret_cast<float2*>(&sf[(tl0 + 8) * CPAD + hl]) = v1;
        }
    }
    __syncthreads();

    if (tid < BN) {
        const float a = 1.0f / (1.0f + expf(-lamda[h0 + tid]));
        float sc = 0.0f;
#pragma unroll 8
        for (int t = 0; t < CHUNK; ++t) sc = fmaf(a, sc, sf[t * CPAD + tid]);
        g_carry[blockIdx.y * H_DIM + h0 + tid] = sc;
    }
}

// ---------------------------------------------------------------------------
// Scan pass 2: prefetch all 64 carries (MLP), then register chain.
// ---------------------------------------------------------------------------
__global__ __launch_bounds__(256)
void combine_kernel(const float* __restrict__ lamda) {
    const int h = blockIdx.x * blockDim.x + threadIdx.x;
    const float a = 1.0f / (1.0f + expf(-lamda[h]));
    float aC = a;
#pragma unroll
    for (int i = 0; i < 7; ++i) aC *= aC;  // a^128

    float car[NCHUNK];
#pragma unroll
    for (int c = 0; c < NCHUNK; ++c) car[c] = g_carry[c * H_DIM + h];

    float state = 0.0f;
#pragma unroll
    for (int c = 0; c < NCHUNK; ++c) {
        g_init[c * H_DIM + h] = state;
        state = fmaf(aC, state, car[c]);
    }
}

// ---------------------------------------------------------------------------
// Scan pass 3: vectorized (float4 over h), exact per-chunk rerun.
// ---------------------------------------------------------------------------
__global__ __launch_bounds__(256)
void apply_kernel(const float* __restrict__ lamda, float* __restrict__ out) {
    const int h4 = (blockIdx.x * blockDim.x + threadIdx.x) * 4;
    const int c = blockIdx.y;
    float4 lam = *reinterpret_cast<const float4*>(&lamda[h4]);
    float4 a;
    a.x = 1.0f / (1.0f + expf(-lam.x));
    a.y = 1.0f / (1.0f + expf(-lam.y));
    a.z = 1.0f / (1.0f + expf(-lam.z));
    a.w = 1.0f / (1.0f + expf(-lam.w));
    float4 s = *reinterpret_cast<const float4*>(&g_init[c * H_DIM + h4]);
    const size_t base = (size_t)c * CHUNK * H_DIM + h4;
#pragma unroll 4
    for (int t = 0; t < CHUNK; ++t) {
        float4 u = *reinterpret_cast<const float4*>(&g_u[base + (size_t)t * H_DIM]);
        s.x = fmaf(a.x, s.x, u.x);
        s.y = fmaf(a.y, s.y, u.y);
        s.z = fmaf(a.z, s.z, u.z);
        s.w = fmaf(a.w, s.w, u.w);
        *reinterpret_cast<float4*>(&out[base + (size_t)t * H_DIM]) = s;
    }
}

// ---------------------------------------------------------------------------
// Host: TMA descriptor creation via runtime entry point
// ---------------------------------------------------------------------------
typedef CUresult (*PFN_tmapEncode)(
    CUtensorMap*, CUtensorMapDataType, cuuint32_t, void*,
    const cuuint64_t*, const cuuint64_t*, const cuuint32_t*, const cuuint32_t*,
    CUtensorMapInterleave, CUtensorMapSwizzle, CUtensorMapL2promotion,
    CUtensorMapFloatOOBfill);

extern "C" void kernel_launch(void* const* d_in, const int* in_sizes, int n_in,
                              void* d_out, int out_size) {
    const float* x     = (const float*)d_in[0];  // [T, D]
    const float* lamda = (const float*)d_in[1];  // [H]
    const float* Bm    = (const float*)d_in[2];  // [H, D]
    float* out = (float*)d_out;                  // [T, H]

    void* pfn = nullptr;
    cudaDriverEntryPointQueryResult qres;
    cudaGetDriverEntryPoint("cuTensorMapEncodeTiled", &pfn, cudaEnableDefault, &qres);
    PFN_tmapEncode encode = (PFN_tmapEncode)pfn;

    void *ax_ptr = nullptr, *bx_ptr = nullptr;
    cudaGetSymbolAddress(&ax_ptr, g_Axh);
    cudaGetSymbolAddress(&bx_ptr, g_Bh);

    CUtensorMap tma_a, tma_b;
    {
        cuuint64_t dims[2]    = {KPACK_A_BYTES, T_DIM};
        cuuint64_t strides[1] = {KPACK_A_BYTES};
        cuuint32_t box[2]     = {128, BM};
        cuuint32_t es[2]      = {1, 1};
        encode(&tma_a, CU_TENSOR_MAP_DATA_TYPE_UINT8, 2, ax_ptr,
               dims, strides, box, es,
               CU_TENSOR_MAP_INTERLEAVE_NONE, CU_TENSOR_MAP_SWIZZLE_128B,
               CU_TENSOR_MAP_L2_PROMOTION_L2_128B, CU_TENSOR_MAP_FLOAT_OOB_FILL_NONE);
    }
    {
        cuuint64_t dims[2]    = {KB_BYTES, H_DIM};
        cuuint64_t strides[1] = {KB_BYTES};
        cuuint32_t box[2]     = {128, BN};
        cuuint32_t es[2]      = {1, 1};
        encode(&tma_b, CU_TENSOR_MAP_DATA_TYPE_UINT8, 2, bx_ptr,
               dims, strides, box, es,
               CU_TENSOR_MAP_INTERLEAVE_NONE, CU_TENSOR_MAP_SWIZZLE_128B,
               CU_TENSOR_MAP_L2_PROMOTION_L2_128B, CU_TENSOR_MAP_FLOAT_OOB_FILL_NONE);
    }

    convert_x_kernel<<<(T_DIM * D_DIM / 4) / 256, 256>>>(x);
    convert_B_kernel<<<(H_DIM * D_DIM / 4) / 256, 256>>>(Bm);

    cudaFuncSetAttribute(gemm_mma_kernel, cudaFuncAttributeMaxDynamicSharedMemorySize, SMEM_TOTAL);
    dim3 ggrid(H_DIM / BN, T_DIM / BM);   // (16, 64)
    gemm_mma_kernel<<<ggrid, 256, SMEM_TOTAL>>>(tma_a, tma_b, lamda);

    combine_kernel<<<H_DIM / 256, 256>>>(lamda);
    dim3 agrid(H_DIM / 4 / 256, NCHUNK);  // (2, 64)
    apply_kernel<<<agrid, 256>>>(lamda, out);
}